// round 11
// baseline (speedup 1.0000x reference)
#include <cuda_runtime.h>

// Problem constants (fixed by reference setup_inputs)
#define HNUM 12
#define PDIM 64
#define DDIM 768
#define NSEQ 1024
#define MAXB 8

// Attention tiling
#define TI 64
#define TJ 128
#define TE 192          // TI + TJ - 1 padded to 192
#define SK 68           // padded row stride (floats) for Q/K/V/E tiles
#define SP 196          // padded row stride (floats) for P tile
// smem floats: Q(64*68) + K(128*68) + V(128*68) + E(192*68) + P(64*196)
#define SMEM_FLOATS ((TI + TJ + TJ + TE) * SK + TI * SP)
#define SMEM_BYTES (SMEM_FLOATS * 4)

// Scratch for projected Q/K/V in [b, h, n, p] layout (75.5 MB total)
__device__ float g_q[MAXB * HNUM * NSEQ * PDIM];
__device__ float g_k[MAXB * HNUM * NSEQ * PDIM];
__device__ float g_v[MAXB * HNUM * NSEQ * PDIM];

// ---------------------------------------------------------------------------
// Kernel 1: C[m][n] = sum_k X[m][k] * W[n][k] + bias[n], scattered to
// out[((b*H + h)*NSEQ + il)*P + p] with b=m>>10, il=m&1023, h=n>>6, p=n&63.
// 128x128x16 tiles, 256 threads, 8x8 register tile per thread.
// ---------------------------------------------------------------------------
__global__ __launch_bounds__(256) void proj_kernel(
    const float* __restrict__ X, const float* __restrict__ W,
    const float* __restrict__ bias, float* __restrict__ out)
{
    __shared__ float Xs[16][132];
    __shared__ float Ws[16][132];

    const int tid = threadIdx.x;
    const int m0 = blockIdx.x * 128;
    const int n0 = blockIdx.y * 128;
    const int ty = tid >> 4;
    const int tx = tid & 15;

    float acc[8][8];
#pragma unroll
    for (int a = 0; a < 8; a++)
#pragma unroll
        for (int c = 0; c < 8; c++) acc[a][c] = 0.f;

    for (int k0 = 0; k0 < DDIM; k0 += 16) {
        __syncthreads();
#pragma unroll
        for (int u = 0; u < 2; u++) {
            int idx = tid + u * 256;
            int row = idx >> 2;
            int q4  = idx & 3;
            float4 xv = *(const float4*)(X + (size_t)(m0 + row) * DDIM + k0 + q4 * 4);
            Xs[q4 * 4 + 0][row] = xv.x;
            Xs[q4 * 4 + 1][row] = xv.y;
            Xs[q4 * 4 + 2][row] = xv.z;
            Xs[q4 * 4 + 3][row] = xv.w;
            float4 wv = *(const float4*)(W + (size_t)(n0 + row) * DDIM + k0 + q4 * 4);
            Ws[q4 * 4 + 0][row] = wv.x;
            Ws[q4 * 4 + 1][row] = wv.y;
            Ws[q4 * 4 + 2][row] = wv.z;
            Ws[q4 * 4 + 3][row] = wv.w;
        }
        __syncthreads();
#pragma unroll
        for (int k = 0; k < 16; k++) {
            float av[8], bv[8];
            *(float4*)(av)     = *(const float4*)&Xs[k][ty * 8];
            *(float4*)(av + 4) = *(const float4*)&Xs[k][ty * 8 + 4];
            *(float4*)(bv)     = *(const float4*)&Ws[k][tx * 8];
            *(float4*)(bv + 4) = *(const float4*)&Ws[k][tx * 8 + 4];
#pragma unroll
            for (int a = 0; a < 8; a++)
#pragma unroll
                for (int c = 0; c < 8; c++)
                    acc[a][c] += av[a] * bv[c];
        }
    }

    // Epilogue: add bias, scatter to [b, h, n, p]
#pragma unroll
    for (int a = 0; a < 8; a++) {
        int m  = m0 + ty * 8 + a;
        int bb = m >> 10;
        int il = m & 1023;
#pragma unroll
        for (int c = 0; c < 8; c += 4) {
            int n = n0 + tx * 8 + c;
            int h = n >> 6;
            int p = n & 63;
            float4 v;
            v.x = acc[a][c + 0] + bias[n + 0];
            v.y = acc[a][c + 1] + bias[n + 1];
            v.z = acc[a][c + 2] + bias[n + 2];
            v.w = acc[a][c + 3] + bias[n + 3];
            *(float4*)(out + (((size_t)(bb * HNUM + h) * NSEQ + il) * PDIM + p)) = v;
        }
    }
}

// ---------------------------------------------------------------------------
// Kernel 2: flash-style attention with relative-key bias.
// Block = (b, h, 64-query tile). Loops over 128-key tiles.
// bias[i][j] = q_i . dist_emb[i - j + 1023] is computed per j-tile as a
// 64x192 GEMM P = Q_tile @ E_sub^T, then gathered along diagonals.
// softmax((QK^T + bias) * 1/8), then @ V with online renormalization.
// ---------------------------------------------------------------------------
__global__ __launch_bounds__(256) void attn_kernel(
    const float* __restrict__ Qg, const float* __restrict__ Kg,
    const float* __restrict__ Vg, const float* __restrict__ Eg,
    float* __restrict__ out)
{
    extern __shared__ float sm[];
    float* Qs = sm;                   // TI x SK
    float* Ks = Qs + TI * SK;         // TJ x SK
    float* Vs = Ks + TJ * SK;         // TJ x SK
    float* Es = Vs + TJ * SK;         // TE x SK
    float* Ps = Es + TE * SK;         // TI x SP

    const int tid = threadIdx.x;
    const int ty = tid >> 4;          // 0..15 -> query rows ty*4 .. ty*4+3
    const int tx = tid & 15;          // 0..15 -> key cols tx*8 .. tx*8+7
    const int i0 = blockIdx.x * TI;
    const int h  = blockIdx.y;
    const int bb = blockIdx.z;
    const int bh = bb * HNUM + h;

    const float* Qbase = Qg + ((size_t)bh * NSEQ + i0) * PDIM;
    const float* Kbase = Kg + (size_t)bh * NSEQ * PDIM;
    const float* Vbase = Vg + (size_t)bh * NSEQ * PDIM;

    // Load Q tile (64 x 64)
#pragma unroll
    for (int u = 0; u < 4; u++) {
        int idx = tid + u * 256;
        int r  = idx >> 4;
        int c4 = idx & 15;
        *(float4*)&Qs[r * SK + c4 * 4] = *(const float4*)(Qbase + r * PDIM + c4 * 4);
    }

    float m_run[4], l_run[4], o[4][4];
#pragma unroll
    for (int a = 0; a < 4; a++) {
        m_run[a] = -1e30f;
        l_run[a] = 0.f;
#pragma unroll
        for (int c = 0; c < 4; c++) o[a][c] = 0.f;
    }

    for (int j0 = 0; j0 < NSEQ; j0 += TJ) {
        __syncthreads();  // previous iteration's smem reads complete

        // Load K, V tiles (128 x 64 each)
#pragma unroll
        for (int u = 0; u < 8; u++) {
            int idx = tid + u * 256;
            int r  = idx >> 4;
            int c4 = idx & 15;
            *(float4*)&Ks[r * SK + c4 * 4] =
                *(const float4*)(Kbase + (size_t)(j0 + r) * PDIM + c4 * 4);
            *(float4*)&Vs[r * SK + c4 * 4] =
                *(const float4*)(Vbase + (size_t)(j0 + r) * PDIM + c4 * 4);
        }
        // Load E tile: dist_emb rows [ebase, ebase+191], ebase = i0-j0+896.
        // For valid (i,j) pairs the used indices are always in [0, 2046];
        // row 191 can be out of range but is never gathered — clamp it.
        int ebase = i0 - j0 + (MAXB * 0) + 896;
#pragma unroll
        for (int u = 0; u < 12; u++) {
            int idx = tid + u * 256;
            int r  = idx >> 4;
            int c4 = idx & 15;
            int er = ebase + r;
            if (er > 2046) er = 2046;
            if (er < 0) er = 0;
            *(float4*)&Es[r * SK + c4 * 4] =
                *(const float4*)(Eg + (size_t)er * PDIM + c4 * 4);
        }
        __syncthreads();

        // Phase A: s[a][b] = Q(ty*4+a) . K(tx*8+b)
        float s[4][8];
#pragma unroll
        for (int a = 0; a < 4; a++)
#pragma unroll
            for (int b = 0; b < 8; b++) s[a][b] = 0.f;

#pragma unroll
        for (int d4 = 0; d4 < 16; d4++) {
            float4 qa[4];
#pragma unroll
            for (int a = 0; a < 4; a++)
                qa[a] = *(const float4*)&Qs[(ty * 4 + a) * SK + d4 * 4];
#pragma unroll
            for (int b = 0; b < 8; b++) {
                float4 kb = *(const float4*)&Ks[(tx * 8 + b) * SK + d4 * 4];
#pragma unroll
                for (int a = 0; a < 4; a++)
                    s[a][b] += qa[a].x * kb.x + qa[a].y * kb.y +
                               qa[a].z * kb.z + qa[a].w * kb.w;
            }
        }

        // Phase B: P[a][t] = Q(ty*4+a) . E(tx*12+c), t = tx*12+c in [0,192)
        {
            float pc[4][12];
#pragma unroll
            for (int a = 0; a < 4; a++)
#pragma unroll
                for (int c = 0; c < 12; c++) pc[a][c] = 0.f;

#pragma unroll
            for (int d4 = 0; d4 < 16; d4++) {
                float4 qa[4];
#pragma unroll
                for (int a = 0; a < 4; a++)
                    qa[a] = *(const float4*)&Qs[(ty * 4 + a) * SK + d4 * 4];
#pragma unroll
                for (int c = 0; c < 12; c++) {
                    float4 eb = *(const float4*)&Es[(tx * 12 + c) * SK + d4 * 4];
#pragma unroll
                    for (int a = 0; a < 4; a++)
                        pc[a][c] += qa[a].x * eb.x + qa[a].y * eb.y +
                                    qa[a].z * eb.z + qa[a].w * eb.w;
                }
            }
#pragma unroll
            for (int a = 0; a < 4; a++)
#pragma unroll
                for (int c = 0; c < 12; c++)
                    Ps[(ty * 4 + a) * SP + tx * 12 + c] = pc[a][c];
        }
        __syncthreads();

        // Gather diagonal bias and scale: s = (s + P[ii][ii-jl+127]) / 8
#pragma unroll
        for (int a = 0; a < 4; a++) {
            int ii = ty * 4 + a;
#pragma unroll
            for (int b = 0; b < 8; b++) {
                int jl = tx * 8 + b;
                s[a][b] = (s[a][b] + Ps[ii * SP + (ii - jl + 127)]) * 0.125f;
            }
        }
        __syncthreads();  // all gathers done before Ps is overwritten with p

        // Online softmax update (row = 64 cols across the 16 tx lanes)
#pragma unroll
        for (int a = 0; a < 4; a++) {
            float mx = s[a][0];
#pragma unroll
            for (int b = 1; b < 8; b++) mx = fmaxf(mx, s[a][b]);
#pragma unroll
            for (int off = 1; off < 16; off <<= 1)
                mx = fmaxf(mx, __shfl_xor_sync(0xffffffffu, mx, off));
            float m_new = fmaxf(m_run[a], mx);
            float scale = __expf(m_run[a] - m_new);
            m_run[a] = m_new;
            float rs = 0.f;
#pragma unroll
            for (int b = 0; b < 8; b++) {
                s[a][b] = __expf(s[a][b] - m_new);
                rs += s[a][b];
            }
#pragma unroll
            for (int off = 1; off < 16; off <<= 1)
                rs += __shfl_xor_sync(0xffffffffu, rs, off);
            l_run[a] = l_run[a] * scale + rs;
#pragma unroll
            for (int c = 0; c < 4; c++) o[a][c] *= scale;
        }

        // Store p into Ps (64 x 128 region)
#pragma unroll
        for (int a = 0; a < 4; a++)
#pragma unroll
            for (int b = 0; b < 8; b++)
                Ps[(ty * 4 + a) * SP + tx * 8 + b] = s[a][b];
        __syncthreads();

        // PV: o[a][c] += sum_jl p[ii][jl] * V[jl][tx*4+c]
#pragma unroll 4
        for (int jl = 0; jl < TJ; jl++) {
            float4 v4 = *(const float4*)&Vs[jl * SK + tx * 4];
#pragma unroll
            for (int a = 0; a < 4; a++) {
                float pa = Ps[(ty * 4 + a) * SP + jl];
                o[a][0] += pa * v4.x;
                o[a][1] += pa * v4.y;
                o[a][2] += pa * v4.z;
                o[a][3] += pa * v4.w;
            }
        }
    }

    // Write output: out[b][i][h*64 + dd]
#pragma unroll
    for (int a = 0; a < 4; a++) {
        int i = i0 + ty * 4 + a;
        float inv = 1.f / l_run[a];
        float4 vo;
        vo.x = o[a][0] * inv;
        vo.y = o[a][1] * inv;
        vo.z = o[a][2] * inv;
        vo.w = o[a][3] * inv;
        *(float4*)(out + ((size_t)bb * NSEQ + i) * DDIM + h * PDIM + tx * 4) = vo;
    }
}

// ---------------------------------------------------------------------------
extern "C" void kernel_launch(void* const* d_in, const int* in_sizes, int n_in,
                              void* d_out, int out_size)
{
    const float* x  = (const float*)d_in[0];
    const float* wq = (const float*)d_in[1];
    const float* bq = (const float*)d_in[2];
    const float* wk = (const float*)d_in[3];
    const float* bk = (const float*)d_in[4];
    const float* wv = (const float*)d_in[5];
    const float* bv = (const float*)d_in[6];
    const float* de = (const float*)d_in[7];
    float* out = (float*)d_out;

    int B = in_sizes[0] / (NSEQ * DDIM);   // 8

    float *qs, *ks, *vs;
    cudaGetSymbolAddress((void**)&qs, g_q);
    cudaGetSymbolAddress((void**)&ks, g_k);
    cudaGetSymbolAddress((void**)&vs, g_v);

    cudaFuncSetAttribute(attn_kernel,
                         cudaFuncAttributeMaxDynamicSharedMemorySize, SMEM_BYTES);

    dim3 g1(B * NSEQ / 128, DDIM / 128);
    proj_kernel<<<g1, 256>>>(x, wq, bq, qs);
    proj_kernel<<<g1, 256>>>(x, wk, bk, ks);
    proj_kernel<<<g1, 256>>>(x, wv, bv, vs);

    dim3 g2(NSEQ / TI, HNUM, B);
    attn_kernel<<<g2, 256, SMEM_BYTES>>>(qs, ks, vs, de, out);
}

// round 12
// speedup vs baseline: 2.1710x; 2.1710x over previous
#include <cuda_runtime.h>

// Problem constants (fixed by reference setup_inputs)
#define HNUM 12
#define PDIM 64
#define DDIM 768
#define NSEQ 1024
#define MAXB 8

// Attention tiling
#define TI 128
#define TJ 128
#define SK 68            // padded row stride (floats) for Q/K/V/E tiles
#define SPP 132          // padded row stride (floats) for P tile (aliases E)
#define EROWS 256        // E window: 255 used rows, 256 allocated
// smem floats: Q(128) + K(128) + V(128) + E(256) rows, SK floats each
#define SMEM_FLOATS ((TI + TJ + TJ + EROWS) * SK)
#define SMEM_BYTES (SMEM_FLOATS * 4)

// Scratch for projected Q/K/V in [b, h, n, p] layout
__device__ float g_q[MAXB * HNUM * NSEQ * PDIM];
__device__ float g_k[MAXB * HNUM * NSEQ * PDIM];
__device__ float g_v[MAXB * HNUM * NSEQ * PDIM];

// ---------------------------------------------------------------------------
// Kernel 1: C[m][n] = (sum_k X[m][k] * W[n][k] + bias[n]) * scale, scattered
// to out[((b*H + h)*NSEQ + il)*P + p]. 128x128x16 tiles, 256 threads, 8x8
// register tile per thread. scale folds the softmax 1/sqrt(P) into Q.
// ---------------------------------------------------------------------------
__global__ __launch_bounds__(256) void proj_kernel(
    const float* __restrict__ X, const float* __restrict__ W,
    const float* __restrict__ bias, float* __restrict__ out, float scale)
{
    __shared__ float Xs[16][132];
    __shared__ float Ws[16][132];

    const int tid = threadIdx.x;
    const int m0 = blockIdx.x * 128;
    const int n0 = blockIdx.y * 128;
    const int ty = tid >> 4;
    const int tx = tid & 15;

    float acc[8][8];
#pragma unroll
    for (int a = 0; a < 8; a++)
#pragma unroll
        for (int c = 0; c < 8; c++) acc[a][c] = 0.f;

    for (int k0 = 0; k0 < DDIM; k0 += 16) {
        __syncthreads();
#pragma unroll
        for (int u = 0; u < 2; u++) {
            int idx = tid + u * 256;
            int row = idx >> 2;
            int q4  = idx & 3;
            float4 xv = *(const float4*)(X + (size_t)(m0 + row) * DDIM + k0 + q4 * 4);
            Xs[q4 * 4 + 0][row] = xv.x;
            Xs[q4 * 4 + 1][row] = xv.y;
            Xs[q4 * 4 + 2][row] = xv.z;
            Xs[q4 * 4 + 3][row] = xv.w;
            float4 wv = *(const float4*)(W + (size_t)(n0 + row) * DDIM + k0 + q4 * 4);
            Ws[q4 * 4 + 0][row] = wv.x;
            Ws[q4 * 4 + 1][row] = wv.y;
            Ws[q4 * 4 + 2][row] = wv.z;
            Ws[q4 * 4 + 3][row] = wv.w;
        }
        __syncthreads();
#pragma unroll
        for (int k = 0; k < 16; k++) {
            float av[8], bv[8];
            *(float4*)(av)     = *(const float4*)&Xs[k][ty * 8];
            *(float4*)(av + 4) = *(const float4*)&Xs[k][ty * 8 + 4];
            *(float4*)(bv)     = *(const float4*)&Ws[k][tx * 8];
            *(float4*)(bv + 4) = *(const float4*)&Ws[k][tx * 8 + 4];
#pragma unroll
            for (int a = 0; a < 8; a++)
#pragma unroll
                for (int c = 0; c < 8; c++)
                    acc[a][c] += av[a] * bv[c];
        }
    }

#pragma unroll
    for (int a = 0; a < 8; a++) {
        int m  = m0 + ty * 8 + a;
        int bb = m >> 10;
        int il = m & 1023;
#pragma unroll
        for (int c = 0; c < 8; c += 4) {
            int n = n0 + tx * 8 + c;
            int h = n >> 6;
            int p = n & 63;
            float4 v;
            v.x = (acc[a][c + 0] + bias[n + 0]) * scale;
            v.y = (acc[a][c + 1] + bias[n + 1]) * scale;
            v.z = (acc[a][c + 2] + bias[n + 2]) * scale;
            v.w = (acc[a][c + 3] + bias[n + 3]) * scale;
            *(float4*)(out + (((size_t)(bb * HNUM + h) * NSEQ + il) * PDIM + p)) = v;
        }
    }
}

// ---------------------------------------------------------------------------
// Kernel 2: flash attention with fused relative-key bias.
// Block = (b, h, 128-query tile), 256 threads (16x16), 8x8 microtile.
// s[a][b] = Q[r].K[c] + Q[r].E[r-c+127]  (Q pre-scaled by 1/8 in proj)
// The 8x8 microtile spans exactly 15 diagonals -> 15 E-row loads per d4.
// Ks/Es are XOR-swizzled (rows 8 apart would otherwise share a bank).
// p tile reuses the E smem region (dead after the fused phase).
// ---------------------------------------------------------------------------
__global__ __launch_bounds__(256) void attn_kernel(
    const float* __restrict__ Qg, const float* __restrict__ Kg,
    const float* __restrict__ Vg, const float* __restrict__ Eg,
    float* __restrict__ out)
{
    extern __shared__ float sm[];
    float* Qs = sm;                    // TI x SK (unswizzled)
    float* Ks = Qs + TI * SK;          // TJ x SK (swizzled)
    float* Vs = Ks + TJ * SK;          // TJ x SK (unswizzled)
    float* Es = Vs + TJ * SK;          // EROWS x SK (swizzled); aliased by Ps
    float* Ps = Es;                    // TI x SPP

    const int tid = threadIdx.x;
    const int ty = tid >> 4;           // rows ty*8 .. ty*8+7
    const int tx = tid & 15;           // cols tx*8 .. tx*8+7
    const int i0 = blockIdx.x * TI;
    const int h  = blockIdx.y;
    const int bb = blockIdx.z;
    const int bh = bb * HNUM + h;

    const float* Qbase = Qg + ((size_t)bh * NSEQ + i0) * PDIM;
    const float* Kbase = Kg + (size_t)bh * NSEQ * PDIM;
    const float* Vbase = Vg + (size_t)bh * NSEQ * PDIM;

    // Load Q tile (128 x 64), unswizzled
#pragma unroll
    for (int u = 0; u < 8; u++) {
        int idx = tid + u * 256;
        int r  = idx >> 4;
        int c4 = idx & 15;
        *(float4*)&Qs[r * SK + c4 * 4] = *(const float4*)(Qbase + r * PDIM + c4 * 4);
    }

    float m_run[8], l_run[8], o[8][4];
#pragma unroll
    for (int a = 0; a < 8; a++) {
        m_run[a] = -1e30f;
        l_run[a] = 0.f;
#pragma unroll
        for (int c = 0; c < 4; c++) o[a][c] = 0.f;
    }

    // Thread's E-row base: diag(a,b) = (ty-tx)*8 + 127 + a - b = ebt + (a-b+7)
    const int ebt = (ty - tx) * 8 + 120;

    for (int j0 = 0; j0 < NSEQ; j0 += TJ) {
        __syncthreads();  // prior iteration's Ps/Vs reads complete

        // Load K (swizzled), V (plain): 128 x 64 each
#pragma unroll
        for (int u = 0; u < 8; u++) {
            int idx = tid + u * 256;
            int r  = idx >> 4;
            int c4 = idx & 15;
            int cs = c4 ^ ((r >> 3) & 7);
            *(float4*)&Ks[r * SK + cs * 4] =
                *(const float4*)(Kbase + (size_t)(j0 + r) * PDIM + c4 * 4);
            *(float4*)&Vs[r * SK + c4 * 4] =
                *(const float4*)(Vbase + (size_t)(j0 + r) * PDIM + c4 * 4);
        }
        // Load E window rows [ebase, ebase+254] (always within [0,2046]),
        // swizzled. Row 255 unused.
        const int ebase = i0 - j0 + 896;
#pragma unroll
        for (int u = 0; u < 16; u++) {
            int idx = tid + u * 256;
            int r  = idx >> 4;
            int c4 = idx & 15;
            if (r < 255) {
                int cs = c4 ^ ((r >> 3) & 7);
                *(float4*)&Es[r * SK + cs * 4] =
                    *(const float4*)(Eg + (size_t)(ebase + r) * PDIM + c4 * 4);
            }
        }
        __syncthreads();

        // Fused S = QK^T + bias (Q already carries the 1/8 scale)
        float s[8][8];
#pragma unroll
        for (int a = 0; a < 8; a++)
#pragma unroll
            for (int b = 0; b < 8; b++) s[a][b] = 0.f;

#pragma unroll
        for (int d4 = 0; d4 < 16; d4++) {
            float4 qa[8];
#pragma unroll
            for (int a = 0; a < 8; a++)
                qa[a] = *(const float4*)&Qs[(ty * 8 + a) * SK + d4 * 4];
            // QK: rows tx*8+b of Ks, swizzle term (r>>3)&7 == tx&7
#pragma unroll
            for (int b = 0; b < 8; b++) {
                float4 kb = *(const float4*)
                    &Ks[(tx * 8 + b) * SK + ((d4 ^ (tx & 7)) * 4)];
#pragma unroll
                for (int a = 0; a < 8; a++)
                    s[a][b] += qa[a].x * kb.x + qa[a].y * kb.y +
                               qa[a].z * kb.z + qa[a].w * kb.w;
            }
            // Bias: 15 diagonals; dd = a-b+7 -> b = a+7-dd
#pragma unroll
            for (int dd = 0; dd < 15; dd++) {
                int re = ebt + dd;
                float4 eb = *(const float4*)
                    &Es[re * SK + ((d4 ^ ((re >> 3) & 7)) * 4)];
#pragma unroll
                for (int a = 0; a < 8; a++) {
                    int b = a + 7 - dd;
                    if (b >= 0 && b < 8)
                        s[a][b] += qa[a].x * eb.x + qa[a].y * eb.y +
                                   qa[a].z * eb.z + qa[a].w * eb.w;
                }
            }
        }

        // Online softmax (row = 128 cols across the 16 tx lanes)
#pragma unroll
        for (int a = 0; a < 8; a++) {
            float mx = s[a][0];
#pragma unroll
            for (int b = 1; b < 8; b++) mx = fmaxf(mx, s[a][b]);
#pragma unroll
            for (int off = 1; off < 16; off <<= 1)
                mx = fmaxf(mx, __shfl_xor_sync(0xffffffffu, mx, off));
            float m_new = fmaxf(m_run[a], mx);
            float scl = __expf(m_run[a] - m_new);
            m_run[a] = m_new;
            float rs = 0.f;
#pragma unroll
            for (int b = 0; b < 8; b++) {
                s[a][b] = __expf(s[a][b] - m_new);
                rs += s[a][b];
            }
#pragma unroll
            for (int off = 1; off < 16; off <<= 1)
                rs += __shfl_xor_sync(0xffffffffu, rs, off);
            l_run[a] = l_run[a] * scl + rs;
#pragma unroll
            for (int c = 0; c < 4; c++) o[a][c] *= scl;
        }

        __syncthreads();  // all Es reads finished before overwrite with p

        // Store p into Ps (128 x 128, stride SPP) — overwrites E region
#pragma unroll
        for (int a = 0; a < 8; a++) {
#pragma unroll
            for (int b4 = 0; b4 < 2; b4++) {
                float4 pv;
                pv.x = s[a][b4 * 4 + 0];
                pv.y = s[a][b4 * 4 + 1];
                pv.z = s[a][b4 * 4 + 2];
                pv.w = s[a][b4 * 4 + 3];
                *(float4*)&Ps[(ty * 8 + a) * SPP + tx * 8 + b4 * 4] = pv;
            }
        }
        __syncthreads();

        // PV: o[a][c] += sum_jl p[r][jl] * V[jl][tx*4+c], float4 over jl
#pragma unroll 2
        for (int jl4 = 0; jl4 < TJ / 4; jl4++) {
            float4 v0 = *(const float4*)&Vs[(jl4 * 4 + 0) * SK + tx * 4];
            float4 v1 = *(const float4*)&Vs[(jl4 * 4 + 1) * SK + tx * 4];
            float4 v2 = *(const float4*)&Vs[(jl4 * 4 + 2) * SK + tx * 4];
            float4 v3 = *(const float4*)&Vs[(jl4 * 4 + 3) * SK + tx * 4];
#pragma unroll
            for (int a = 0; a < 8; a++) {
                float4 p4 = *(const float4*)&Ps[(ty * 8 + a) * SPP + jl4 * 4];
                o[a][0] += p4.x * v0.x + p4.y * v1.x + p4.z * v2.x + p4.w * v3.x;
                o[a][1] += p4.x * v0.y + p4.y * v1.y + p4.z * v2.y + p4.w * v3.y;
                o[a][2] += p4.x * v0.z + p4.y * v1.z + p4.z * v2.z + p4.w * v3.z;
                o[a][3] += p4.x * v0.w + p4.y * v1.w + p4.z * v2.w + p4.w * v3.w;
            }
        }
    }

    // Write output: out[b][i][h*64 + tx*4 + c]
#pragma unroll
    for (int a = 0; a < 8; a++) {
        int i = i0 + ty * 8 + a;
        float inv = 1.f / l_run[a];
        float4 vo;
        vo.x = o[a][0] * inv;
        vo.y = o[a][1] * inv;
        vo.z = o[a][2] * inv;
        vo.w = o[a][3] * inv;
        *(float4*)(out + ((size_t)bb * NSEQ + i) * DDIM + h * PDIM + tx * 4) = vo;
    }
}

// ---------------------------------------------------------------------------
extern "C" void kernel_launch(void* const* d_in, const int* in_sizes, int n_in,
                              void* d_out, int out_size)
{
    const float* x  = (const float*)d_in[0];
    const float* wq = (const float*)d_in[1];
    const float* bq = (const float*)d_in[2];
    const float* wk = (const float*)d_in[3];
    const float* bk = (const float*)d_in[4];
    const float* wv = (const float*)d_in[5];
    const float* bv = (const float*)d_in[6];
    const float* de = (const float*)d_in[7];
    float* out = (float*)d_out;

    int B = in_sizes[0] / (NSEQ * DDIM);   // 8

    float *qs, *ks, *vs;
    cudaGetSymbolAddress((void**)&qs, g_q);
    cudaGetSymbolAddress((void**)&ks, g_k);
    cudaGetSymbolAddress((void**)&vs, g_v);

    cudaFuncSetAttribute(attn_kernel,
                         cudaFuncAttributeMaxDynamicSharedMemorySize, SMEM_BYTES);

    dim3 g1(B * NSEQ / 128, DDIM / 128);
    proj_kernel<<<g1, 256>>>(x, wq, bq, qs, 0.125f);   // fold 1/sqrt(64) into Q
    proj_kernel<<<g1, 256>>>(x, wk, bk, ks, 1.0f);
    proj_kernel<<<g1, 256>>>(x, wv, bv, vs, 1.0f);

    dim3 g2(NSEQ / TI, HNUM, B);
    attn_kernel<<<g2, 256, SMEM_BYTES>>>(qs, ks, vs, de, out);
}

// round 14
// speedup vs baseline: 2.9070x; 1.3390x over previous
#include <cuda_runtime.h>
#include <cuda_bf16.h>
#include <cstdint>

// Problem constants
#define HNUM 12
#define PDIM 64
#define DDIM 768
#define NSEQ 1024
#define MAXB 8
#define KCAT (3 * DDIM)     // concatenated K for bf16-split GEMM (2304)
#define NCH (KCAT / 64)     // 36 K-chunks of 64 bf16

// Attention tiling (unchanged — at fp32 roofline)
#define TI 128
#define TJ 128
#define SK 68
#define SPP 132
#define EROWS 256
#define SMEM_FLOATS ((TI + TJ + TJ + EROWS) * SK)
#define SMEM_BYTES (SMEM_FLOATS * 4)

// GEMM smem: 2 stages x (A 16KB + B 16KB) = 64KB; epilogue 128x132 fp32 = 67.6KB
#define GEMM_SMEM (128 * 132 * 4 + 1024)

// Device scratch
__device__ float g_q[MAXB * HNUM * NSEQ * PDIM];
__device__ float g_k[MAXB * HNUM * NSEQ * PDIM];
__device__ float g_v[MAXB * HNUM * NSEQ * PDIM];
__device__ __nv_bfloat16 g_xcat[MAXB * NSEQ * KCAT];    // [hi | lo | hi]
__device__ __nv_bfloat16 g_wcat[3 * DDIM * KCAT];       // [hi | hi | lo] per weight

// ---------------------------------------------------------------------------
// PTX helpers (sm_80-era only: cp.async, ldmatrix, mma.sync — no "a" features)
// ---------------------------------------------------------------------------
__device__ __forceinline__ uint32_t smaddr(const void* p) {
    return (uint32_t)__cvta_generic_to_shared(p);
}
__device__ __forceinline__ void cp16(uint32_t dst, const void* src) {
    asm volatile("cp.async.cg.shared.global [%0], [%1], 16;" :: "r"(dst), "l"(src));
}
__device__ __forceinline__ void cp_commit() {
    asm volatile("cp.async.commit_group;" ::: "memory");
}
__device__ __forceinline__ void cp_wait0() {
    asm volatile("cp.async.wait_group 0;" ::: "memory");
}
__device__ __forceinline__ void cp_wait1() {
    asm volatile("cp.async.wait_group 1;" ::: "memory");
}
__device__ __forceinline__ void ldm_x4(uint32_t& r0, uint32_t& r1,
                                       uint32_t& r2, uint32_t& r3, uint32_t a) {
    asm volatile("ldmatrix.sync.aligned.m8n8.x4.shared.b16 {%0,%1,%2,%3}, [%4];"
                 : "=r"(r0), "=r"(r1), "=r"(r2), "=r"(r3) : "r"(a));
}
__device__ __forceinline__ void mma_bf16(float* c, const uint32_t* a,
                                         uint32_t b0, uint32_t b1) {
    asm volatile(
        "mma.sync.aligned.m16n8k16.row.col.f32.bf16.bf16.f32 "
        "{%0,%1,%2,%3}, {%4,%5,%6,%7}, {%8,%9}, {%0,%1,%2,%3};"
        : "+f"(c[0]), "+f"(c[1]), "+f"(c[2]), "+f"(c[3])
        : "r"(a[0]), "r"(a[1]), "r"(a[2]), "r"(a[3]), "r"(b0), "r"(b1));
}

// ---------------------------------------------------------------------------
// Split kernel: fp32 -> bf16 hi/lo, written to three K-slots of the cat buffer.
// ---------------------------------------------------------------------------
__global__ __launch_bounds__(256) void split_kernel(
    const float* __restrict__ src, __nv_bfloat16* __restrict__ dst,
    int n4, int hi2_off, int lo_off)
{
    int i = blockIdx.x * 256 + threadIdx.x;
    if (i >= n4) return;
    int row = i / (DDIM / 4);
    int c4  = i - row * (DDIM / 4);
    float4 v = ((const float4*)src)[i];

    __nv_bfloat16 h0 = __float2bfloat16(v.x);
    __nv_bfloat16 h1 = __float2bfloat16(v.y);
    __nv_bfloat16 h2 = __float2bfloat16(v.z);
    __nv_bfloat16 h3 = __float2bfloat16(v.w);
    __nv_bfloat16 l0 = __float2bfloat16(v.x - __bfloat162float(h0));
    __nv_bfloat16 l1 = __float2bfloat16(v.y - __bfloat162float(h1));
    __nv_bfloat16 l2 = __float2bfloat16(v.z - __bfloat162float(h2));
    __nv_bfloat16 l3 = __float2bfloat16(v.w - __bfloat162float(h3));

    uint2 hi, lo;
    hi.x = ((uint32_t)__bfloat16_as_ushort(h1) << 16) | __bfloat16_as_ushort(h0);
    hi.y = ((uint32_t)__bfloat16_as_ushort(h3) << 16) | __bfloat16_as_ushort(h2);
    lo.x = ((uint32_t)__bfloat16_as_ushort(l1) << 16) | __bfloat16_as_ushort(l0);
    lo.y = ((uint32_t)__bfloat16_as_ushort(l3) << 16) | __bfloat16_as_ushort(l2);

    size_t base = (size_t)row * KCAT + c4 * 4;
    *(uint2*)(dst + base)           = hi;
    *(uint2*)(dst + base + hi2_off) = hi;
    *(uint2*)(dst + base + lo_off)  = lo;
}

// ---------------------------------------------------------------------------
// HMMA GEMM: C[m][n] = sum_k' Xcat[m][k'] * Wcat[n][k'] (bf16, fp32 acc)
// == fp32 X@W^T to ~1.6e-5. 128x128 block tile, 8 warps x (64x32) warp tiles,
// mma.sync.m16n8k16, cp.async double-buffered, XOR-swizzled smem + ldmatrix.
// grid = (Mtiles, 6, 3) with z selecting {q,k,v}; epilogue bias+scale+scatter.
// ---------------------------------------------------------------------------
__global__ __launch_bounds__(256) void gemm_kernel(
    const __nv_bfloat16* __restrict__ Xc, const __nv_bfloat16* __restrict__ Wc,
    const float* __restrict__ bq, const float* __restrict__ bk,
    const float* __restrict__ bv,
    float* __restrict__ oq, float* __restrict__ ok, float* __restrict__ ov)
{
    extern __shared__ char smraw[];

    const int tid = threadIdx.x;
    const int wid = tid >> 5;
    const int lid = tid & 31;
    const int wr = wid >> 2;           // 0..1 : warp row (64 rows)
    const int wc = wid & 3;            // 0..3 : warp col (32 cols)
    const int z  = blockIdx.z;
    const int m0 = blockIdx.x * 128;
    const int n0 = blockIdx.y * 128;

    const float* bias = (z == 0) ? bq : (z == 1) ? bk : bv;
    float* out        = (z == 0) ? oq : (z == 1) ? ok : ov;
    const float scale = (z == 0) ? 0.125f : 1.0f;

    uint32_t raw = smaddr(smraw);
    uint32_t sb  = (raw + 127) & ~127u;
    // stage s: A at sb + s*32768, B at sb + s*32768 + 16384
    const __nv_bfloat16* Asrc = Xc + (size_t)m0 * KCAT;
    const __nv_bfloat16* Bsrc = Wc + (size_t)z * DDIM * KCAT + (size_t)n0 * KCAT;

    // async copy: 2048 x 16B per stage (A 1024 + B 1024), 8 per thread
    auto load_chunk = [&](int c, int s) {
        const int kc = c * 64;                  // bf16 k-offset
        const uint32_t base = sb + s * 32768;
#pragma unroll
        for (int u = 0; u < 8; u++) {
            int seg = tid + u * 256;            // 0..2047
            int isB = seg >> 10;                // 0: A, 1: B
            int r   = (seg >> 3) & 127;
            int ch  = seg & 7;
            uint32_t dst = base + isB * 16384 + r * 128 + ((ch ^ (r & 7)) * 16);
            const __nv_bfloat16* src = (isB ? Bsrc : Asrc) +
                (size_t)r * KCAT + kc + ch * 8;
            cp16(dst, src);
        }
        cp_commit();
    };

    // accumulators: 4 m-tiles x 4 n-tiles x 4 fp32
    float acc[4][4][4];
#pragma unroll
    for (int i = 0; i < 4; i++)
#pragma unroll
        for (int j = 0; j < 4; j++)
#pragma unroll
            for (int q = 0; q < 4; q++) acc[i][j][q] = 0.f;

    // ldmatrix per-lane addressing: row = tilebase + (l&15), 16B-chunk
    // = (2*kk + (l>>4)) ^ (l&7)
    const int lrow = lid & 15;
    const int lhalf = lid >> 4;
    const int lxor = lid & 7;

    load_chunk(0, 0);

    for (int c = 0; c < NCH; c++) {
        const int s = c & 1;
        if (c + 1 < NCH) {
            load_chunk(c + 1, s ^ 1);
            cp_wait1();                 // chunk c complete, c+1 may be in flight
        } else {
            cp_wait0();
        }
        __syncthreads();

        const uint32_t Abase = sb + s * 32768;
        const uint32_t Bbase = Abase + 16384;

#pragma unroll
        for (int kk = 0; kk < 4; kk++) {
            const uint32_t chsel = ((uint32_t)(2 * kk + lhalf) ^ lxor) * 16;
            // A fragments: 4 m16 tiles
            uint32_t afr[4][4];
#pragma unroll
            for (int mt = 0; mt < 4; mt++) {
                uint32_t a = Abase + (wr * 64 + mt * 16 + lrow) * 128 + chsel;
                ldm_x4(afr[mt][0], afr[mt][1], afr[mt][2], afr[mt][3], a);
            }
            // B fragments: 2 x4 loads cover 4 n8 tiles
            uint32_t bfr[8];
#pragma unroll
            for (int np = 0; np < 2; np++) {
                uint32_t a = Bbase + (wc * 32 + np * 16 + lrow) * 128 + chsel;
                // r0=(n0:8,k0:8) r1=(n8:16,k0:8) r2=(n0:8,k8:16) r3=(n8:16,k8:16)
                ldm_x4(bfr[np * 4 + 0], bfr[np * 4 + 1],
                       bfr[np * 4 + 2], bfr[np * 4 + 3], a);
            }
#pragma unroll
            for (int mt = 0; mt < 4; mt++) {
#pragma unroll
                for (int nt = 0; nt < 4; nt++) {
                    int np = nt >> 1, sub = nt & 1;
                    mma_bf16(acc[mt][nt], afr[mt],
                             bfr[np * 4 + sub], bfr[np * 4 + 2 + sub]);
                }
            }
        }
        __syncthreads();   // all reads done before next overwrite of this stage
    }

    // ---- epilogue: regs -> smem (128x132) -> coalesced bias+scale scatter ----
    float* Dst = (float*)(smraw + (sb - raw));
#pragma unroll
    for (int mt = 0; mt < 4; mt++) {
#pragma unroll
        for (int nt = 0; nt < 4; nt++) {
            int row = wr * 64 + mt * 16 + (lid >> 2);
            int col = wc * 32 + nt * 8 + 2 * (lid & 3);
            *(float2*)&Dst[row * 132 + col] =
                make_float2(acc[mt][nt][0], acc[mt][nt][1]);
            *(float2*)&Dst[(row + 8) * 132 + col] =
                make_float2(acc[mt][nt][2], acc[mt][nt][3]);
        }
    }
    __syncthreads();

#pragma unroll
    for (int u = 0; u < 16; u++) {
        int item = tid + u * 256;
        int row = item >> 5;
        int c4  = item & 31;
        float4 d = *(const float4*)&Dst[row * 132 + c4 * 4];
        int n = n0 + c4 * 4;
        int m = m0 + row;
        int bb2 = m >> 10, il = m & 1023;
        int h = n >> 6, p = n & 63;
        float4 v;
        v.x = (d.x + bias[n + 0]) * scale;
        v.y = (d.y + bias[n + 1]) * scale;
        v.z = (d.z + bias[n + 2]) * scale;
        v.w = (d.w + bias[n + 3]) * scale;
        *(float4*)(out + (((size_t)(bb2 * HNUM + h) * NSEQ + il) * PDIM + p)) = v;
    }
}

// ---------------------------------------------------------------------------
// Flash attention with fused relative-key bias (unchanged — fp32 roofline).
// ---------------------------------------------------------------------------
__global__ __launch_bounds__(256) void attn_kernel(
    const float* __restrict__ Qg, const float* __restrict__ Kg,
    const float* __restrict__ Vg, const float* __restrict__ Eg,
    float* __restrict__ out)
{
    extern __shared__ float sm[];
    float* Qs = sm;
    float* Ks = Qs + TI * SK;
    float* Vs = Ks + TJ * SK;
    float* Es = Vs + TJ * SK;
    float* Ps = Es;

    const int tid = threadIdx.x;
    const int ty = tid >> 4;
    const int tx = tid & 15;
    const int i0 = blockIdx.x * TI;
    const int h  = blockIdx.y;
    const int bb = blockIdx.z;
    const int bh = bb * HNUM + h;

    const float* Qbase = Qg + ((size_t)bh * NSEQ + i0) * PDIM;
    const float* Kbase = Kg + (size_t)bh * NSEQ * PDIM;
    const float* Vbase = Vg + (size_t)bh * NSEQ * PDIM;

#pragma unroll
    for (int u = 0; u < 8; u++) {
        int idx = tid + u * 256;
        int r  = idx >> 4;
        int c4 = idx & 15;
        *(float4*)&Qs[r * SK + c4 * 4] = *(const float4*)(Qbase + r * PDIM + c4 * 4);
    }

    float m_run[8], l_run[8], o[8][4];
#pragma unroll
    for (int a = 0; a < 8; a++) {
        m_run[a] = -1e30f;
        l_run[a] = 0.f;
#pragma unroll
        for (int c = 0; c < 4; c++) o[a][c] = 0.f;
    }

    const int ebt = (ty - tx) * 8 + 120;

    for (int j0 = 0; j0 < NSEQ; j0 += TJ) {
        __syncthreads();

#pragma unroll
        for (int u = 0; u < 8; u++) {
            int idx = tid + u * 256;
            int r  = idx >> 4;
            int c4 = idx & 15;
            int cs = c4 ^ ((r >> 3) & 7);
            *(float4*)&Ks[r * SK + cs * 4] =
                *(const float4*)(Kbase + (size_t)(j0 + r) * PDIM + c4 * 4);
            *(float4*)&Vs[r * SK + c4 * 4] =
                *(const float4*)(Vbase + (size_t)(j0 + r) * PDIM + c4 * 4);
        }
        const int ebase = i0 - j0 + 896;
#pragma unroll
        for (int u = 0; u < 16; u++) {
            int idx = tid + u * 256;
            int r  = idx >> 4;
            int c4 = idx & 15;
            if (r < 255) {
                int cs = c4 ^ ((r >> 3) & 7);
                *(float4*)&Es[r * SK + cs * 4] =
                    *(const float4*)(Eg + (size_t)(ebase + r) * PDIM + c4 * 4);
            }
        }
        __syncthreads();

        float s[8][8];
#pragma unroll
        for (int a = 0; a < 8; a++)
#pragma unroll
            for (int b = 0; b < 8; b++) s[a][b] = 0.f;

#pragma unroll
        for (int d4 = 0; d4 < 16; d4++) {
            float4 qa[8];
#pragma unroll
            for (int a = 0; a < 8; a++)
                qa[a] = *(const float4*)&Qs[(ty * 8 + a) * SK + d4 * 4];
#pragma unroll
            for (int b = 0; b < 8; b++) {
                float4 kb = *(const float4*)
                    &Ks[(tx * 8 + b) * SK + ((d4 ^ (tx & 7)) * 4)];
#pragma unroll
                for (int a = 0; a < 8; a++)
                    s[a][b] += qa[a].x * kb.x + qa[a].y * kb.y +
                               qa[a].z * kb.z + qa[a].w * kb.w;
            }
#pragma unroll
            for (int dd = 0; dd < 15; dd++) {
                int re = ebt + dd;
                float4 eb = *(const float4*)
                    &Es[re * SK + ((d4 ^ ((re >> 3) & 7)) * 4)];
#pragma unroll
                for (int a = 0; a < 8; a++) {
                    int b = a + 7 - dd;
                    if (b >= 0 && b < 8)
                        s[a][b] += qa[a].x * eb.x + qa[a].y * eb.y +
                                   qa[a].z * eb.z + qa[a].w * eb.w;
                }
            }
        }

#pragma unroll
        for (int a = 0; a < 8; a++) {
            float mx = s[a][0];
#pragma unroll
            for (int b = 1; b < 8; b++) mx = fmaxf(mx, s[a][b]);
#pragma unroll
            for (int off = 1; off < 16; off <<= 1)
                mx = fmaxf(mx, __shfl_xor_sync(0xffffffffu, mx, off));
            float m_new = fmaxf(m_run[a], mx);
            float scl = __expf(m_run[a] - m_new);
            m_run[a] = m_new;
            float rs = 0.f;
#pragma unroll
            for (int b = 0; b < 8; b++) {
                s[a][b] = __expf(s[a][b] - m_new);
                rs += s[a][b];
            }
#pragma unroll
            for (int off = 1; off < 16; off <<= 1)
                rs += __shfl_xor_sync(0xffffffffu, rs, off);
            l_run[a] = l_run[a] * scl + rs;
#pragma unroll
            for (int c = 0; c < 4; c++) o[a][c] *= scl;
        }

        __syncthreads();

#pragma unroll
        for (int a = 0; a < 8; a++) {
#pragma unroll
            for (int b4 = 0; b4 < 2; b4++) {
                float4 pv;
                pv.x = s[a][b4 * 4 + 0];
                pv.y = s[a][b4 * 4 + 1];
                pv.z = s[a][b4 * 4 + 2];
                pv.w = s[a][b4 * 4 + 3];
                *(float4*)&Ps[(ty * 8 + a) * SPP + tx * 8 + b4 * 4] = pv;
            }
        }
        __syncthreads();

#pragma unroll 2
        for (int jl4 = 0; jl4 < TJ / 4; jl4++) {
            float4 v0 = *(const float4*)&Vs[(jl4 * 4 + 0) * SK + tx * 4];
            float4 v1 = *(const float4*)&Vs[(jl4 * 4 + 1) * SK + tx * 4];
            float4 v2 = *(const float4*)&Vs[(jl4 * 4 + 2) * SK + tx * 4];
            float4 v3 = *(const float4*)&Vs[(jl4 * 4 + 3) * SK + tx * 4];
#pragma unroll
            for (int a = 0; a < 8; a++) {
                float4 p4 = *(const float4*)&Ps[(ty * 8 + a) * SPP + jl4 * 4];
                o[a][0] += p4.x * v0.x + p4.y * v1.x + p4.z * v2.x + p4.w * v3.x;
                o[a][1] += p4.x * v0.y + p4.y * v1.y + p4.z * v2.y + p4.w * v3.y;
                o[a][2] += p4.x * v0.z + p4.y * v1.z + p4.z * v2.z + p4.w * v3.z;
                o[a][3] += p4.x * v0.w + p4.y * v1.w + p4.z * v2.w + p4.w * v3.w;
            }
        }
    }

#pragma unroll
    for (int a = 0; a < 8; a++) {
        int i = i0 + ty * 8 + a;
        float inv = 1.f / l_run[a];
        float4 vo;
        vo.x = o[a][0] * inv;
        vo.y = o[a][1] * inv;
        vo.z = o[a][2] * inv;
        vo.w = o[a][3] * inv;
        *(float4*)(out + ((size_t)bb * NSEQ + i) * DDIM + h * PDIM + tx * 4) = vo;
    }
}

// ---------------------------------------------------------------------------
extern "C" void kernel_launch(void* const* d_in, const int* in_sizes, int n_in,
                              void* d_out, int out_size)
{
    const float* x  = (const float*)d_in[0];
    const float* wq = (const float*)d_in[1];
    const float* bq = (const float*)d_in[2];
    const float* wk = (const float*)d_in[3];
    const float* bk = (const float*)d_in[4];
    const float* wv = (const float*)d_in[5];
    const float* bv = (const float*)d_in[6];
    const float* de = (const float*)d_in[7];
    float* out = (float*)d_out;

    int B = in_sizes[0] / (NSEQ * DDIM);   // 8

    float *qs, *ks, *vs;
    __nv_bfloat16 *xcat, *wcat;
    cudaGetSymbolAddress((void**)&qs, g_q);
    cudaGetSymbolAddress((void**)&ks, g_k);
    cudaGetSymbolAddress((void**)&vs, g_v);
    cudaGetSymbolAddress((void**)&xcat, g_xcat);
    cudaGetSymbolAddress((void**)&wcat, g_wcat);

    cudaFuncSetAttribute(attn_kernel,
                         cudaFuncAttributeMaxDynamicSharedMemorySize, SMEM_BYTES);
    cudaFuncSetAttribute(gemm_kernel,
                         cudaFuncAttributeMaxDynamicSharedMemorySize, GEMM_SMEM);

    int nx4 = B * NSEQ * (DDIM / 4);
    int nw4 = DDIM * (DDIM / 4);
    split_kernel<<<(nx4 + 255) / 256, 256>>>(x, xcat, nx4, 2 * DDIM, DDIM);
    split_kernel<<<(nw4 + 255) / 256, 256>>>(wq, wcat + 0 * (size_t)DDIM * KCAT,
                                             nw4, DDIM, 2 * DDIM);
    split_kernel<<<(nw4 + 255) / 256, 256>>>(wk, wcat + 1 * (size_t)DDIM * KCAT,
                                             nw4, DDIM, 2 * DDIM);
    split_kernel<<<(nw4 + 255) / 256, 256>>>(wv, wcat + 2 * (size_t)DDIM * KCAT,
                                             nw4, DDIM, 2 * DDIM);

    dim3 g1(B * NSEQ / 128, DDIM / 128, 3);
    gemm_kernel<<<g1, 256, GEMM_SMEM>>>(xcat, wcat, bq, bk, bv, qs, ks, vs);

    dim3 g2(NSEQ / TI, HNUM, B);
    attn_kernel<<<g2, 256, SMEM_BYTES>>>(qs, ks, vs, de, out);
}

// round 15
// speedup vs baseline: 4.0473x; 1.3922x over previous
#include <cuda_runtime.h>
#include <cuda_bf16.h>
#include <cstdint>

// Problem constants
#define HNUM 12
#define PDIM 64
#define DDIM 768
#define NSEQ 1024
#define MAXB 8
#define KCAT (3 * DDIM)
#define NCH (KCAT / 64)

// proj GEMM smem
#define GEMM_SMEM (128 * 132 * 4 + 1024)

// attn smem layout (byte offsets into dynamic smem)
#define O_QHI 0
#define O_QLO 16384
#define O_KHI 32768
#define O_KLO 49152
#define O_VHI 65536
#define O_VLO 81920
#define O_EHI 98304
#define O_ELO 131072
#define O_PST 163840        // fp32 128x66 (aliases PHI/PLO region, temporally disjoint)
#define O_PHI 163840
#define O_PLO 196608
#define ATTN_SMEM 229376

// Device scratch
__device__ __nv_bfloat16 g_qhi[MAXB * HNUM * NSEQ * PDIM];
__device__ __nv_bfloat16 g_qlo[MAXB * HNUM * NSEQ * PDIM];
__device__ __nv_bfloat16 g_khi[MAXB * HNUM * NSEQ * PDIM];
__device__ __nv_bfloat16 g_klo[MAXB * HNUM * NSEQ * PDIM];
__device__ __nv_bfloat16 g_vhi[MAXB * HNUM * NSEQ * PDIM];
__device__ __nv_bfloat16 g_vlo[MAXB * HNUM * NSEQ * PDIM];
__device__ __nv_bfloat16 g_ehi[2048 * PDIM];
__device__ __nv_bfloat16 g_elo[2048 * PDIM];
__device__ __nv_bfloat16 g_xcat[MAXB * NSEQ * KCAT];
__device__ __nv_bfloat16 g_wcat[3 * DDIM * KCAT];

// ---------------------------------------------------------------------------
// PTX helpers (sm_80-era: cp.async, ldmatrix, mma.sync)
// ---------------------------------------------------------------------------
__device__ __forceinline__ uint32_t smaddr(const void* p) {
    return (uint32_t)__cvta_generic_to_shared(p);
}
__device__ __forceinline__ void cp16(uint32_t dst, const void* src) {
    asm volatile("cp.async.cg.shared.global [%0], [%1], 16;" :: "r"(dst), "l"(src));
}
__device__ __forceinline__ void cp_commit() {
    asm volatile("cp.async.commit_group;" ::: "memory");
}
__device__ __forceinline__ void cp_wait0() {
    asm volatile("cp.async.wait_group 0;" ::: "memory");
}
__device__ __forceinline__ void cp_wait1() {
    asm volatile("cp.async.wait_group 1;" ::: "memory");
}
__device__ __forceinline__ void ldm_x4(uint32_t* r, uint32_t a) {
    asm volatile("ldmatrix.sync.aligned.m8n8.x4.shared.b16 {%0,%1,%2,%3}, [%4];"
                 : "=r"(r[0]), "=r"(r[1]), "=r"(r[2]), "=r"(r[3]) : "r"(a));
}
__device__ __forceinline__ void ldm_x4t(uint32_t* r, uint32_t a) {
    asm volatile("ldmatrix.sync.aligned.m8n8.x4.trans.shared.b16 {%0,%1,%2,%3}, [%4];"
                 : "=r"(r[0]), "=r"(r[1]), "=r"(r[2]), "=r"(r[3]) : "r"(a));
}
__device__ __forceinline__ void mma_bf16(float* c, const uint32_t* a,
                                         uint32_t b0, uint32_t b1) {
    asm volatile(
        "mma.sync.aligned.m16n8k16.row.col.f32.bf16.bf16.f32 "
        "{%0,%1,%2,%3}, {%4,%5,%6,%7}, {%8,%9}, {%0,%1,%2,%3};"
        : "+f"(c[0]), "+f"(c[1]), "+f"(c[2]), "+f"(c[3])
        : "r"(a[0]), "r"(a[1]), "r"(a[2]), "r"(a[3]), "r"(b0), "r"(b1));
}
__device__ __forceinline__ uint32_t pack_bf16x2(float a, float b) {
    __nv_bfloat16 ha = __float2bfloat16(a), hb = __float2bfloat16(b);
    return ((uint32_t)__bfloat16_as_ushort(hb) << 16) | __bfloat16_as_ushort(ha);
}

// ---------------------------------------------------------------------------
// Split kernel: fp32 -> bf16 hi/lo into the 3-slot concatenated buffer.
// ---------------------------------------------------------------------------
__global__ __launch_bounds__(256) void split_kernel(
    const float* __restrict__ src, __nv_bfloat16* __restrict__ dst,
    int n4, int hi2_off, int lo_off)
{
    int i = blockIdx.x * 256 + threadIdx.x;
    if (i >= n4) return;
    int row = i / (DDIM / 4);
    int c4  = i - row * (DDIM / 4);
    float4 v = ((const float4*)src)[i];

    float hx = __bfloat162float(__float2bfloat16(v.x));
    float hy = __bfloat162float(__float2bfloat16(v.y));
    float hz = __bfloat162float(__float2bfloat16(v.z));
    float hw = __bfloat162float(__float2bfloat16(v.w));
    uint2 hi, lo;
    hi.x = pack_bf16x2(v.x, v.y);
    hi.y = pack_bf16x2(v.z, v.w);
    lo.x = pack_bf16x2(v.x - hx, v.y - hy);
    lo.y = pack_bf16x2(v.z - hz, v.w - hw);

    size_t base = (size_t)row * KCAT + c4 * 4;
    *(uint2*)(dst + base)           = hi;
    *(uint2*)(dst + base + hi2_off) = hi;
    *(uint2*)(dst + base + lo_off)  = lo;
}

// dist_emb split: 2047x64 fp32 -> 2048x64 bf16 hi/lo (row 2047 zero pad)
__global__ __launch_bounds__(256) void esplit_kernel(
    const float* __restrict__ de, __nv_bfloat16* __restrict__ ehi,
    __nv_bfloat16* __restrict__ elo)
{
    int i = blockIdx.x * 256 + threadIdx.x;   // over 2048*16 float4 items
    if (i >= 2048 * 16) return;
    int row = i >> 4, c4 = i & 15;
    float4 v = (row < 2047) ? ((const float4*)de)[row * 16 + c4]
                            : make_float4(0.f, 0.f, 0.f, 0.f);
    float hx = __bfloat162float(__float2bfloat16(v.x));
    float hy = __bfloat162float(__float2bfloat16(v.y));
    float hz = __bfloat162float(__float2bfloat16(v.z));
    float hw = __bfloat162float(__float2bfloat16(v.w));
    uint2 hi, lo;
    hi.x = pack_bf16x2(v.x, v.y);
    hi.y = pack_bf16x2(v.z, v.w);
    lo.x = pack_bf16x2(v.x - hx, v.y - hy);
    lo.y = pack_bf16x2(v.z - hz, v.w - hw);
    size_t o = (size_t)row * PDIM + c4 * 4;
    *(uint2*)(ehi + o) = hi;
    *(uint2*)(elo + o) = lo;
}

// ---------------------------------------------------------------------------
// HMMA projection GEMM (as R14), epilogue now writes bf16 hi/lo arrays.
// ---------------------------------------------------------------------------
__global__ __launch_bounds__(256) void gemm_kernel(
    const __nv_bfloat16* __restrict__ Xc, const __nv_bfloat16* __restrict__ Wc,
    const float* __restrict__ bq, const float* __restrict__ bk,
    const float* __restrict__ bv,
    __nv_bfloat16* __restrict__ qhi, __nv_bfloat16* __restrict__ qlo,
    __nv_bfloat16* __restrict__ khi, __nv_bfloat16* __restrict__ klo,
    __nv_bfloat16* __restrict__ vhi, __nv_bfloat16* __restrict__ vlo)
{
    extern __shared__ char smraw[];

    const int tid = threadIdx.x;
    const int wid = tid >> 5;
    const int lid = tid & 31;
    const int wr = wid >> 2;
    const int wc = wid & 3;
    const int z  = blockIdx.z;
    const int m0 = blockIdx.x * 128;
    const int n0 = blockIdx.y * 128;

    const float* bias = (z == 0) ? bq : (z == 1) ? bk : bv;
    __nv_bfloat16* ohi = (z == 0) ? qhi : (z == 1) ? khi : vhi;
    __nv_bfloat16* olo = (z == 0) ? qlo : (z == 1) ? klo : vlo;
    const float scale = (z == 0) ? 0.125f : 1.0f;

    uint32_t raw = smaddr(smraw);
    uint32_t sb  = (raw + 127) & ~127u;
    const __nv_bfloat16* Asrc = Xc + (size_t)m0 * KCAT;
    const __nv_bfloat16* Bsrc = Wc + (size_t)z * DDIM * KCAT + (size_t)n0 * KCAT;

    auto load_chunk = [&](int c, int s) {
        const int kc = c * 64;
        const uint32_t base = sb + s * 32768;
#pragma unroll
        for (int u = 0; u < 8; u++) {
            int seg = tid + u * 256;
            int isB = seg >> 10;
            int r   = (seg >> 3) & 127;
            int ch  = seg & 7;
            uint32_t dst = base + isB * 16384 + r * 128 + ((ch ^ (r & 7)) * 16);
            const __nv_bfloat16* src = (isB ? Bsrc : Asrc) +
                (size_t)r * KCAT + kc + ch * 8;
            cp16(dst, src);
        }
        cp_commit();
    };

    float acc[4][4][4];
#pragma unroll
    for (int i = 0; i < 4; i++)
#pragma unroll
        for (int j = 0; j < 4; j++)
#pragma unroll
            for (int q = 0; q < 4; q++) acc[i][j][q] = 0.f;

    const int lrow = lid & 15;
    const int lhalf = lid >> 4;
    const int lxor = lid & 7;

    load_chunk(0, 0);

    for (int c = 0; c < NCH; c++) {
        const int s = c & 1;
        if (c + 1 < NCH) { load_chunk(c + 1, s ^ 1); cp_wait1(); }
        else             { cp_wait0(); }
        __syncthreads();

        const uint32_t Abase = sb + s * 32768;
        const uint32_t Bbase = Abase + 16384;

#pragma unroll
        for (int kk = 0; kk < 4; kk++) {
            const uint32_t chsel = ((uint32_t)(2 * kk + lhalf) ^ lxor) * 16;
            uint32_t afr[4][4];
#pragma unroll
            for (int mt = 0; mt < 4; mt++)
                ldm_x4(afr[mt], Abase + (wr * 64 + mt * 16 + lrow) * 128 + chsel);
            uint32_t bfr[8];
#pragma unroll
            for (int np = 0; np < 2; np++)
                ldm_x4(bfr + np * 4, Bbase + (wc * 32 + np * 16 + lrow) * 128 + chsel);
#pragma unroll
            for (int mt = 0; mt < 4; mt++)
#pragma unroll
                for (int nt = 0; nt < 4; nt++) {
                    int np = nt >> 1, sub = nt & 1;
                    mma_bf16(acc[mt][nt], afr[mt],
                             bfr[np * 4 + sub], bfr[np * 4 + 2 + sub]);
                }
        }
        __syncthreads();
    }

    float* Dst = (float*)(smraw + (sb - raw));
#pragma unroll
    for (int mt = 0; mt < 4; mt++)
#pragma unroll
        for (int nt = 0; nt < 4; nt++) {
            int row = wr * 64 + mt * 16 + (lid >> 2);
            int col = wc * 32 + nt * 8 + 2 * (lid & 3);
            *(float2*)&Dst[row * 132 + col] =
                make_float2(acc[mt][nt][0], acc[mt][nt][1]);
            *(float2*)&Dst[(row + 8) * 132 + col] =
                make_float2(acc[mt][nt][2], acc[mt][nt][3]);
        }
    __syncthreads();

#pragma unroll
    for (int u = 0; u < 16; u++) {
        int item = tid + u * 256;
        int row = item >> 5;
        int c4  = item & 31;
        float4 d = *(const float4*)&Dst[row * 132 + c4 * 4];
        int n = n0 + c4 * 4;
        int m = m0 + row;
        int bb2 = m >> 10, il = m & 1023;
        int h = n >> 6, p = n & 63;
        float vx = (d.x + bias[n + 0]) * scale;
        float vy = (d.y + bias[n + 1]) * scale;
        float vz = (d.z + bias[n + 2]) * scale;
        float vw = (d.w + bias[n + 3]) * scale;
        float hx = __bfloat162float(__float2bfloat16(vx));
        float hy = __bfloat162float(__float2bfloat16(vy));
        float hz = __bfloat162float(__float2bfloat16(vz));
        float hw = __bfloat162float(__float2bfloat16(vw));
        uint2 hi, lo;
        hi.x = pack_bf16x2(vx, vy);
        hi.y = pack_bf16x2(vz, vw);
        lo.x = pack_bf16x2(vx - hx, vy - hy);
        lo.y = pack_bf16x2(vz - hz, vw - hw);
        size_t o = (((size_t)(bb2 * HNUM + h) * NSEQ + il) * PDIM + p);
        *(uint2*)(ohi + o) = hi;
        *(uint2*)(olo + o) = lo;
    }
}

// ---------------------------------------------------------------------------
// HMMA flash attention with fused relative-key bias, 3-term bf16 split.
// Block = (b,h, 128 q-rows), 8 warps, warp tile 16x128.
// ---------------------------------------------------------------------------
__global__ __launch_bounds__(256) void attn_kernel(
    const __nv_bfloat16* __restrict__ qhi, const __nv_bfloat16* __restrict__ qlo,
    const __nv_bfloat16* __restrict__ khi, const __nv_bfloat16* __restrict__ klo,
    const __nv_bfloat16* __restrict__ vhi, const __nv_bfloat16* __restrict__ vlo,
    const __nv_bfloat16* __restrict__ ehi, const __nv_bfloat16* __restrict__ elo,
    float* __restrict__ out)
{
    extern __shared__ char smc[];
    const uint32_t sb = smaddr(smc);

    const int tid = threadIdx.x;
    const int w   = tid >> 5;
    const int lid = tid & 31;
    const int lrow = lid & 15, lhalf = lid >> 4;
    const int lq = lid >> 2, lr4 = lid & 3;
    const int i0 = blockIdx.x * 128;
    const int h  = blockIdx.y;
    const int bb = blockIdx.z;
    const int bh = bb * HNUM + h;

    const size_t qoff   = ((size_t)bh * NSEQ + i0) * PDIM;
    const size_t kvbase = (size_t)bh * NSEQ * PDIM;

    // ---- Q tiles (once) ----
#pragma unroll
    for (int u = 0; u < 8; u++) {
        int t  = u >> 2;                       // 0: hi, 1: lo
        int idx = tid + u * 256;
        int r  = (idx >> 3) & 127;
        int ch = idx & 7;
        uint32_t dst = sb + (t ? O_QLO : O_QHI) + r * 128 + ((ch ^ (r & 7)) << 4);
        cp16(dst, (t ? qlo : qhi) + qoff + (size_t)r * PDIM + ch * 8);
    }
    cp_commit();

    float oacc[8][4];
#pragma unroll
    for (int nt = 0; nt < 8; nt++)
#pragma unroll
        for (int q = 0; q < 4; q++) oacc[nt][q] = 0.f;
    float m_run[2] = {-1e30f, -1e30f}, l_run[2] = {0.f, 0.f};

    float* PSTf = (float*)(smc + O_PST);

    for (int jt = 0; jt < 8; jt++) {
        const int j0 = jt * 128;
        __syncthreads();   // all reads of K/V/E/p from prior iteration done

        // ---- loads: K,V (hi/lo) + E window (hi/lo) ----
#pragma unroll
        for (int u = 0; u < 16; u++) {         // K/V: 4 tiles x 4 u's
            int t = u >> 2;                    // 0 KHI,1 KLO,2 VHI,3 VLO
            int idx = tid + u * 256;
            int r  = (idx >> 3) & 127;
            int ch = idx & 7;
            uint32_t dst = sb + O_KHI + t * 16384 + r * 128 + ((ch ^ (r & 7)) << 4);
            const __nv_bfloat16* s =
                (t == 0 ? khi : t == 1 ? klo : t == 2 ? vhi : vlo);
            cp16(dst, s + kvbase + (size_t)(j0 + r) * PDIM + ch * 8);
        }
        const int ebase = i0 - j0 + 896;
#pragma unroll
        for (int u = 0; u < 16; u++) {         // E: 2 tiles x 8 u's
            int t = u >> 3;
            int idx = tid + (u & 7) * 256;     // 2048 chunks per tile
            int r  = (idx >> 3) & 255;
            int ch = idx & 7;
            uint32_t dst = sb + O_EHI + t * 32768 + r * 128 + ((ch ^ (r & 7)) << 4);
            cp16(dst, (t ? elo : ehi) + (size_t)(ebase + r) * PDIM + ch * 8);
        }
        cp_commit();
        cp_wait0();
        __syncthreads();

        // ---- S = QK^T (3-term split) ----
        float s[16][4];
#pragma unroll
        for (int nt = 0; nt < 16; nt++)
#pragma unroll
            for (int q = 0; q < 4; q++) s[nt][q] = 0.f;

#pragma unroll
        for (int kk = 0; kk < 4; kk++) {
            const uint32_t chsw = ((uint32_t)(2 * kk + lhalf) ^ (lrow & 7)) << 4;
            uint32_t ah[4], al[4], kb[8][4];
            ldm_x4(ah, sb + O_QHI + (w * 16 + lrow) * 128 + chsw);
            ldm_x4(al, sb + O_QLO + (w * 16 + lrow) * 128 + chsw);
#pragma unroll
            for (int np = 0; np < 8; np++)
                ldm_x4(kb[np], sb + O_KHI + (np * 16 + lrow) * 128 + chsw);
#pragma unroll
            for (int nt = 0; nt < 16; nt++)
                mma_bf16(s[nt], ah, kb[nt >> 1][nt & 1], kb[nt >> 1][2 + (nt & 1)]);
#pragma unroll
            for (int nt = 0; nt < 16; nt++)
                mma_bf16(s[nt], al, kb[nt >> 1][nt & 1], kb[nt >> 1][2 + (nt & 1)]);
#pragma unroll
            for (int np = 0; np < 8; np++)
                ldm_x4(kb[np], sb + O_KLO + (np * 16 + lrow) * 128 + chsw);
#pragma unroll
            for (int nt = 0; nt < 16; nt++)
                mma_bf16(s[nt], ah, kb[nt >> 1][nt & 1], kb[nt >> 1][2 + (nt & 1)]);
        }

        // ---- bias: 4 chunks of 64 P-cols ----
#pragma unroll 1
        for (int ck = 0; ck < 4; ck++) {
            float p[8][4];
#pragma unroll
            for (int nt = 0; nt < 8; nt++)
#pragma unroll
                for (int q = 0; q < 4; q++) p[nt][q] = 0.f;

#pragma unroll
            for (int kk = 0; kk < 4; kk++) {
                const uint32_t chsw = ((uint32_t)(2 * kk + lhalf) ^ (lrow & 7)) << 4;
                uint32_t ah[4], al[4], eb[4][4];
                ldm_x4(ah, sb + O_QHI + (w * 16 + lrow) * 128 + chsw);
                ldm_x4(al, sb + O_QLO + (w * 16 + lrow) * 128 + chsw);
#pragma unroll
                for (int np = 0; np < 4; np++)
                    ldm_x4(eb[np], sb + O_EHI +
                           (ck * 64 + np * 16 + lrow) * 128 + chsw);
#pragma unroll
                for (int nt = 0; nt < 8; nt++)
                    mma_bf16(p[nt], ah, eb[nt >> 1][nt & 1], eb[nt >> 1][2 + (nt & 1)]);
#pragma unroll
                for (int nt = 0; nt < 8; nt++)
                    mma_bf16(p[nt], al, eb[nt >> 1][nt & 1], eb[nt >> 1][2 + (nt & 1)]);
#pragma unroll
                for (int np = 0; np < 4; np++)
                    ldm_x4(eb[np], sb + O_ELO +
                           (ck * 64 + np * 16 + lrow) * 128 + chsw);
#pragma unroll
                for (int nt = 0; nt < 8; nt++)
                    mma_bf16(p[nt], ah, eb[nt >> 1][nt & 1], eb[nt >> 1][2 + (nt & 1)]);
            }
            // stage chunk to per-warp PST rows
#pragma unroll
            for (int nt = 0; nt < 8; nt++) {
                int row = w * 16 + lq;
                int col = nt * 8 + 2 * lr4;
                *(float2*)&PSTf[row * 66 + col] = make_float2(p[nt][0], p[nt][1]);
                *(float2*)&PSTf[(row + 8) * 66 + col] = make_float2(p[nt][2], p[nt][3]);
            }
            __syncwarp();
            // diagonal gather into S (own-warp rows only)
#pragma unroll
            for (int nt = 0; nt < 16; nt++)
#pragma unroll
                for (int idx = 0; idx < 4; idx++) {
                    int h2 = idx >> 1, e = idx & 1;
                    int r_loc = w * 16 + lq + h2 * 8;
                    int c = nt * 8 + 2 * lr4 + e;
                    int pw = r_loc - c + 127;
                    if ((pw >> 6) == ck)
                        s[nt][idx] += PSTf[r_loc * 66 + (pw & 63)];
                }
            __syncwarp();
        }

        // ---- online softmax ----
#pragma unroll
        for (int h2 = 0; h2 < 2; h2++) {
            float mx = -1e30f;
#pragma unroll
            for (int nt = 0; nt < 16; nt++)
                mx = fmaxf(mx, fmaxf(s[nt][h2 * 2], s[nt][h2 * 2 + 1]));
            mx = fmaxf(mx, __shfl_xor_sync(0xffffffffu, mx, 1));
            mx = fmaxf(mx, __shfl_xor_sync(0xffffffffu, mx, 2));
            float m_new = fmaxf(m_run[h2], mx);
            float scl = __expf(m_run[h2] - m_new);
            m_run[h2] = m_new;
            float rs = 0.f;
#pragma unroll
            for (int nt = 0; nt < 16; nt++) {
                float e0 = __expf(s[nt][h2 * 2] - m_new);
                float e1 = __expf(s[nt][h2 * 2 + 1] - m_new);
                s[nt][h2 * 2] = e0;
                s[nt][h2 * 2 + 1] = e1;
                rs += e0 + e1;
            }
            rs += __shfl_xor_sync(0xffffffffu, rs, 1);
            rs += __shfl_xor_sync(0xffffffffu, rs, 2);
            l_run[h2] = l_run[h2] * scl + rs;
#pragma unroll
            for (int nt = 0; nt < 8; nt++) {
                oacc[nt][h2 * 2] *= scl;
                oacc[nt][h2 * 2 + 1] *= scl;
            }
        }

        // ---- write p hi/lo tiles (own-warp rows) ----
#pragma unroll
        for (int nt = 0; nt < 16; nt++)
#pragma unroll
            for (int h2 = 0; h2 < 2; h2++) {
                int row = w * 16 + lq + h2 * 8;
                int c = nt * 8 + 2 * lr4;
                float p0 = s[nt][h2 * 2], p1 = s[nt][h2 * 2 + 1];
                float h0 = __bfloat162float(__float2bfloat16(p0));
                float h1 = __bfloat162float(__float2bfloat16(p1));
                uint32_t off = row * 256 + (((c >> 3) ^ (row & 7)) << 4) + (c & 7) * 2;
                *(uint32_t*)(smc + O_PHI + off) = pack_bf16x2(p0, p1);
                *(uint32_t*)(smc + O_PLO + off) = pack_bf16x2(p0 - h0, p1 - h1);
            }
        __syncwarp();

        // ---- PV (3-term split), V via ldmatrix.trans ----
#pragma unroll
        for (int kk = 0; kk < 8; kk++) {
            uint32_t ah[4], al[4], vb[4][4];
            {
                uint32_t chA = (uint32_t)(2 * kk + lhalf);
                uint32_t aoff = (w * 16 + lrow) * 256 + ((chA ^ (lrow & 7)) << 4);
                ldm_x4(ah, sb + O_PHI + aoff);
                ldm_x4(al, sb + O_PLO + aoff);
            }
            const uint32_t vrow = kk * 16 + lrow;
#pragma unroll
            for (int np = 0; np < 4; np++)
                ldm_x4t(vb[np], sb + O_VHI + vrow * 128 +
                        ((((uint32_t)(np * 2 + lhalf)) ^ (lrow & 7)) << 4));
#pragma unroll
            for (int nt = 0; nt < 8; nt++)
                mma_bf16(oacc[nt], ah, vb[nt >> 1][(nt & 1) * 2],
                         vb[nt >> 1][(nt & 1) * 2 + 1]);
#pragma unroll
            for (int nt = 0; nt < 8; nt++)
                mma_bf16(oacc[nt], al, vb[nt >> 1][(nt & 1) * 2],
                         vb[nt >> 1][(nt & 1) * 2 + 1]);
#pragma unroll
            for (int np = 0; np < 4; np++)
                ldm_x4t(vb[np], sb + O_VLO + vrow * 128 +
                        ((((uint32_t)(np * 2 + lhalf)) ^ (lrow & 7)) << 4));
#pragma unroll
            for (int nt = 0; nt < 8; nt++)
                mma_bf16(oacc[nt], ah, vb[nt >> 1][(nt & 1) * 2],
                         vb[nt >> 1][(nt & 1) * 2 + 1]);
        }
    }

    // ---- final normalize + write ----
#pragma unroll
    for (int h2 = 0; h2 < 2; h2++) {
        float inv = 1.f / l_run[h2];
        int r_glob = i0 + w * 16 + lq + h2 * 8;
#pragma unroll
        for (int nt = 0; nt < 8; nt++) {
            int d = nt * 8 + 2 * lr4;
            *(float2*)(out + ((size_t)bb * NSEQ + r_glob) * DDIM + h * PDIM + d) =
                make_float2(oacc[nt][h2 * 2] * inv, oacc[nt][h2 * 2 + 1] * inv);
        }
    }
}

// ---------------------------------------------------------------------------
extern "C" void kernel_launch(void* const* d_in, const int* in_sizes, int n_in,
                              void* d_out, int out_size)
{
    const float* x  = (const float*)d_in[0];
    const float* wq = (const float*)d_in[1];
    const float* bq = (const float*)d_in[2];
    const float* wk = (const float*)d_in[3];
    const float* bk = (const float*)d_in[4];
    const float* wv = (const float*)d_in[5];
    const float* bv = (const float*)d_in[6];
    const float* de = (const float*)d_in[7];
    float* out = (float*)d_out;

    int B = in_sizes[0] / (NSEQ * DDIM);   // 8

    __nv_bfloat16 *xcat, *wcat, *qhi, *qlo, *khi, *klo, *vhi, *vlo, *ehi, *elo;
    cudaGetSymbolAddress((void**)&xcat, g_xcat);
    cudaGetSymbolAddress((void**)&wcat, g_wcat);
    cudaGetSymbolAddress((void**)&qhi, g_qhi);
    cudaGetSymbolAddress((void**)&qlo, g_qlo);
    cudaGetSymbolAddress((void**)&khi, g_khi);
    cudaGetSymbolAddress((void**)&klo, g_klo);
    cudaGetSymbolAddress((void**)&vhi, g_vhi);
    cudaGetSymbolAddress((void**)&vlo, g_vlo);
    cudaGetSymbolAddress((void**)&ehi, g_ehi);
    cudaGetSymbolAddress((void**)&elo, g_elo);

    cudaFuncSetAttribute(gemm_kernel,
                         cudaFuncAttributeMaxDynamicSharedMemorySize, GEMM_SMEM);
    cudaFuncSetAttribute(attn_kernel,
                         cudaFuncAttributeMaxDynamicSharedMemorySize, ATTN_SMEM);

    int nx4 = B * NSEQ * (DDIM / 4);
    int nw4 = DDIM * (DDIM / 4);
    split_kernel<<<(nx4 + 255) / 256, 256>>>(x, xcat, nx4, 2 * DDIM, DDIM);
    split_kernel<<<(nw4 + 255) / 256, 256>>>(wq, wcat + 0 * (size_t)DDIM * KCAT,
                                             nw4, DDIM, 2 * DDIM);
    split_kernel<<<(nw4 + 255) / 256, 256>>>(wk, wcat + 1 * (size_t)DDIM * KCAT,
                                             nw4, DDIM, 2 * DDIM);
    split_kernel<<<(nw4 + 255) / 256, 256>>>(wv, wcat + 2 * (size_t)DDIM * KCAT,
                                             nw4, DDIM, 2 * DDIM);
    esplit_kernel<<<128, 256>>>(de, ehi, elo);

    dim3 g1(B * NSEQ / 128, DDIM / 128, 3);
    gemm_kernel<<<g1, 256, GEMM_SMEM>>>(xcat, wcat, bq, bk, bv,
                                        qhi, qlo, khi, klo, vhi, vlo);

    dim3 g2(NSEQ / 128, HNUM, B);
    attn_kernel<<<g2, 256, ATTN_SMEM>>>(qhi, qlo, khi, klo, vhi, vlo,
                                        ehi, elo, out);
}

// round 16
// speedup vs baseline: 5.2013x; 1.2851x over previous
#include <cuda_runtime.h>
#include <cuda_bf16.h>
#include <cstdint>

// Problem constants
#define HNUM 12
#define PDIM 64
#define DDIM 768
#define NSEQ 1024
#define MAXB 8
#define KCAT (3 * DDIM)
#define NCH (KCAT / 64)

// proj GEMM smem
#define GEMM_SMEM (128 * 132 * 4 + 1024)

// attn smem layout (byte offsets into dynamic smem)
#define O_QHI 0
#define O_QLO 16384
#define O_KHI 32768
#define O_KLO 49152
#define O_VHI 65536
#define O_VLO 81920
#define O_EHI 98304
#define O_ELO 131072
#define O_PST 163840        // per-warp fp32 16x84 stage (aliases PHI/PLO; sync-separated)
#define O_PHI 163840
#define O_PLO 196608
#define ATTN_SMEM 229376

// Device scratch
__device__ __nv_bfloat16 g_qhi[MAXB * HNUM * NSEQ * PDIM];
__device__ __nv_bfloat16 g_qlo[MAXB * HNUM * NSEQ * PDIM];
__device__ __nv_bfloat16 g_khi[MAXB * HNUM * NSEQ * PDIM];
__device__ __nv_bfloat16 g_klo[MAXB * HNUM * NSEQ * PDIM];
__device__ __nv_bfloat16 g_vhi[MAXB * HNUM * NSEQ * PDIM];
__device__ __nv_bfloat16 g_vlo[MAXB * HNUM * NSEQ * PDIM];
__device__ __nv_bfloat16 g_ehi[2048 * PDIM];
__device__ __nv_bfloat16 g_elo[2048 * PDIM];
__device__ __nv_bfloat16 g_xcat[MAXB * NSEQ * KCAT];
__device__ __nv_bfloat16 g_wcat[3 * DDIM * KCAT];

// ---------------------------------------------------------------------------
// PTX helpers
// ---------------------------------------------------------------------------
__device__ __forceinline__ uint32_t smaddr(const void* p) {
    return (uint32_t)__cvta_generic_to_shared(p);
}
__device__ __forceinline__ void cp16(uint32_t dst, const void* src) {
    asm volatile("cp.async.cg.shared.global [%0], [%1], 16;" :: "r"(dst), "l"(src));
}
__device__ __forceinline__ void cp_commit() {
    asm volatile("cp.async.commit_group;" ::: "memory");
}
__device__ __forceinline__ void cp_wait0() {
    asm volatile("cp.async.wait_group 0;" ::: "memory");
}
__device__ __forceinline__ void cp_wait1() {
    asm volatile("cp.async.wait_group 1;" ::: "memory");
}
__device__ __forceinline__ void cp_wait2() {
    asm volatile("cp.async.wait_group 2;" ::: "memory");
}
__device__ __forceinline__ void ldm_x4(uint32_t* r, uint32_t a) {
    asm volatile("ldmatrix.sync.aligned.m8n8.x4.shared.b16 {%0,%1,%2,%3}, [%4];"
                 : "=r"(r[0]), "=r"(r[1]), "=r"(r[2]), "=r"(r[3]) : "r"(a));
}
__device__ __forceinline__ void ldm_x4t(uint32_t* r, uint32_t a) {
    asm volatile("ldmatrix.sync.aligned.m8n8.x4.trans.shared.b16 {%0,%1,%2,%3}, [%4];"
                 : "=r"(r[0]), "=r"(r[1]), "=r"(r[2]), "=r"(r[3]) : "r"(a));
}
__device__ __forceinline__ void mma_bf16(float* c, const uint32_t* a,
                                         uint32_t b0, uint32_t b1) {
    asm volatile(
        "mma.sync.aligned.m16n8k16.row.col.f32.bf16.bf16.f32 "
        "{%0,%1,%2,%3}, {%4,%5,%6,%7}, {%8,%9}, {%0,%1,%2,%3};"
        : "+f"(c[0]), "+f"(c[1]), "+f"(c[2]), "+f"(c[3])
        : "r"(a[0]), "r"(a[1]), "r"(a[2]), "r"(a[3]), "r"(b0), "r"(b1));
}
__device__ __forceinline__ uint32_t pack_bf16x2(float a, float b) {
    __nv_bfloat16 ha = __float2bfloat16(a), hb = __float2bfloat16(b);
    return ((uint32_t)__bfloat16_as_ushort(hb) << 16) | __bfloat16_as_ushort(ha);
}

// ---------------------------------------------------------------------------
// Split kernels
// ---------------------------------------------------------------------------
__global__ __launch_bounds__(256) void split_kernel(
    const float* __restrict__ src, __nv_bfloat16* __restrict__ dst,
    int n4, int hi2_off, int lo_off)
{
    int i = blockIdx.x * 256 + threadIdx.x;
    if (i >= n4) return;
    int row = i / (DDIM / 4);
    int c4  = i - row * (DDIM / 4);
    float4 v = ((const float4*)src)[i];

    float hx = __bfloat162float(__float2bfloat16(v.x));
    float hy = __bfloat162float(__float2bfloat16(v.y));
    float hz = __bfloat162float(__float2bfloat16(v.z));
    float hw = __bfloat162float(__float2bfloat16(v.w));
    uint2 hi, lo;
    hi.x = pack_bf16x2(v.x, v.y);
    hi.y = pack_bf16x2(v.z, v.w);
    lo.x = pack_bf16x2(v.x - hx, v.y - hy);
    lo.y = pack_bf16x2(v.z - hz, v.w - hw);

    size_t base = (size_t)row * KCAT + c4 * 4;
    *(uint2*)(dst + base)           = hi;
    *(uint2*)(dst + base + hi2_off) = hi;
    *(uint2*)(dst + base + lo_off)  = lo;
}

__global__ __launch_bounds__(256) void esplit_kernel(
    const float* __restrict__ de, __nv_bfloat16* __restrict__ ehi,
    __nv_bfloat16* __restrict__ elo)
{
    int i = blockIdx.x * 256 + threadIdx.x;
    if (i >= 2048 * 16) return;
    int row = i >> 4, c4 = i & 15;
    float4 v = (row < 2047) ? ((const float4*)de)[row * 16 + c4]
                            : make_float4(0.f, 0.f, 0.f, 0.f);
    float hx = __bfloat162float(__float2bfloat16(v.x));
    float hy = __bfloat162float(__float2bfloat16(v.y));
    float hz = __bfloat162float(__float2bfloat16(v.z));
    float hw = __bfloat162float(__float2bfloat16(v.w));
    uint2 hi, lo;
    hi.x = pack_bf16x2(v.x, v.y);
    hi.y = pack_bf16x2(v.z, v.w);
    lo.x = pack_bf16x2(v.x - hx, v.y - hy);
    lo.y = pack_bf16x2(v.z - hz, v.w - hw);
    size_t o = (size_t)row * PDIM + c4 * 4;
    *(uint2*)(ehi + o) = hi;
    *(uint2*)(elo + o) = lo;
}

// ---------------------------------------------------------------------------
// HMMA projection GEMM (unchanged from R15).
// ---------------------------------------------------------------------------
__global__ __launch_bounds__(256) void gemm_kernel(
    const __nv_bfloat16* __restrict__ Xc, const __nv_bfloat16* __restrict__ Wc,
    const float* __restrict__ bq, const float* __restrict__ bk,
    const float* __restrict__ bv,
    __nv_bfloat16* __restrict__ qhi, __nv_bfloat16* __restrict__ qlo,
    __nv_bfloat16* __restrict__ khi, __nv_bfloat16* __restrict__ klo,
    __nv_bfloat16* __restrict__ vhi, __nv_bfloat16* __restrict__ vlo)
{
    extern __shared__ char smraw[];

    const int tid = threadIdx.x;
    const int wid = tid >> 5;
    const int lid = tid & 31;
    const int wr = wid >> 2;
    const int wc = wid & 3;
    const int z  = blockIdx.z;
    const int m0 = blockIdx.x * 128;
    const int n0 = blockIdx.y * 128;

    const float* bias = (z == 0) ? bq : (z == 1) ? bk : bv;
    __nv_bfloat16* ohi = (z == 0) ? qhi : (z == 1) ? khi : vhi;
    __nv_bfloat16* olo = (z == 0) ? qlo : (z == 1) ? klo : vlo;
    const float scale = (z == 0) ? 0.125f : 1.0f;

    uint32_t raw = smaddr(smraw);
    uint32_t sb  = (raw + 127) & ~127u;
    const __nv_bfloat16* Asrc = Xc + (size_t)m0 * KCAT;
    const __nv_bfloat16* Bsrc = Wc + (size_t)z * DDIM * KCAT + (size_t)n0 * KCAT;

    auto load_chunk = [&](int c, int s) {
        const int kc = c * 64;
        const uint32_t base = sb + s * 32768;
#pragma unroll
        for (int u = 0; u < 8; u++) {
            int seg = tid + u * 256;
            int isB = seg >> 10;
            int r   = (seg >> 3) & 127;
            int ch  = seg & 7;
            uint32_t dst = base + isB * 16384 + r * 128 + ((ch ^ (r & 7)) * 16);
            const __nv_bfloat16* src = (isB ? Bsrc : Asrc) +
                (size_t)r * KCAT + kc + ch * 8;
            cp16(dst, src);
        }
        cp_commit();
    };

    float acc[4][4][4];
#pragma unroll
    for (int i = 0; i < 4; i++)
#pragma unroll
        for (int j = 0; j < 4; j++)
#pragma unroll
            for (int q = 0; q < 4; q++) acc[i][j][q] = 0.f;

    const int lrow = lid & 15;
    const int lhalf = lid >> 4;
    const int lxor = lid & 7;

    load_chunk(0, 0);

    for (int c = 0; c < NCH; c++) {
        const int s = c & 1;
        if (c + 1 < NCH) { load_chunk(c + 1, s ^ 1); cp_wait1(); }
        else             { cp_wait0(); }
        __syncthreads();

        const uint32_t Abase = sb + s * 32768;
        const uint32_t Bbase = Abase + 16384;

#pragma unroll
        for (int kk = 0; kk < 4; kk++) {
            const uint32_t chsel = ((uint32_t)(2 * kk + lhalf) ^ lxor) * 16;
            uint32_t afr[4][4];
#pragma unroll
            for (int mt = 0; mt < 4; mt++)
                ldm_x4(afr[mt], Abase + (wr * 64 + mt * 16 + lrow) * 128 + chsel);
            uint32_t bfr[8];
#pragma unroll
            for (int np = 0; np < 2; np++)
                ldm_x4(bfr + np * 4, Bbase + (wc * 32 + np * 16 + lrow) * 128 + chsel);
#pragma unroll
            for (int mt = 0; mt < 4; mt++)
#pragma unroll
                for (int nt = 0; nt < 4; nt++) {
                    int np = nt >> 1, sub = nt & 1;
                    mma_bf16(acc[mt][nt], afr[mt],
                             bfr[np * 4 + sub], bfr[np * 4 + 2 + sub]);
                }
        }
        __syncthreads();
    }

    float* Dst = (float*)(smraw + (sb - raw));
#pragma unroll
    for (int mt = 0; mt < 4; mt++)
#pragma unroll
        for (int nt = 0; nt < 4; nt++) {
            int row = wr * 64 + mt * 16 + (lid >> 2);
            int col = wc * 32 + nt * 8 + 2 * (lid & 3);
            *(float2*)&Dst[row * 132 + col] =
                make_float2(acc[mt][nt][0], acc[mt][nt][1]);
            *(float2*)&Dst[(row + 8) * 132 + col] =
                make_float2(acc[mt][nt][2], acc[mt][nt][3]);
        }
    __syncthreads();

#pragma unroll
    for (int u = 0; u < 16; u++) {
        int item = tid + u * 256;
        int row = item >> 5;
        int c4  = item & 31;
        float4 d = *(const float4*)&Dst[row * 132 + c4 * 4];
        int n = n0 + c4 * 4;
        int m = m0 + row;
        int bb2 = m >> 10, il = m & 1023;
        int h = n >> 6, p = n & 63;
        float vx = (d.x + bias[n + 0]) * scale;
        float vy = (d.y + bias[n + 1]) * scale;
        float vz = (d.z + bias[n + 2]) * scale;
        float vw = (d.w + bias[n + 3]) * scale;
        float hx = __bfloat162float(__float2bfloat16(vx));
        float hy = __bfloat162float(__float2bfloat16(vy));
        float hz = __bfloat162float(__float2bfloat16(vz));
        float hw = __bfloat162float(__float2bfloat16(vw));
        uint2 hi, lo;
        hi.x = pack_bf16x2(vx, vy);
        hi.y = pack_bf16x2(vz, vw);
        lo.x = pack_bf16x2(vx - hx, vy - hy);
        lo.y = pack_bf16x2(vz - hz, vw - hw);
        size_t o = (((size_t)(bb2 * HNUM + h) * NSEQ + il) * PDIM + p);
        *(uint2*)(ohi + o) = hi;
        *(uint2*)(olo + o) = lo;
    }
}

// ---------------------------------------------------------------------------
// HMMA flash attention, 3-term bf16 split, per-warp bias window (143 cols),
// cp.async software pipeline (V at top, K after QK, E after gather).
// ---------------------------------------------------------------------------
__global__ __launch_bounds__(256) void attn_kernel(
    const __nv_bfloat16* __restrict__ qhi, const __nv_bfloat16* __restrict__ qlo,
    const __nv_bfloat16* __restrict__ khi, const __nv_bfloat16* __restrict__ klo,
    const __nv_bfloat16* __restrict__ vhi, const __nv_bfloat16* __restrict__ vlo,
    const __nv_bfloat16* __restrict__ ehi, const __nv_bfloat16* __restrict__ elo,
    float* __restrict__ out)
{
    extern __shared__ char smc[];
    const uint32_t sb = smaddr(smc);

    const int tid = threadIdx.x;
    const int w   = tid >> 5;
    const int lid = tid & 31;
    const int lrow = lid & 15, lhalf = lid >> 4;
    const int lq = lid >> 2, lr4 = lid & 3;
    const int i0 = blockIdx.x * 128;
    const int h  = blockIdx.y;
    const int bb = blockIdx.z;
    const int bh = bb * HNUM + h;

    const size_t qoff   = ((size_t)bh * NSEQ + i0) * PDIM;
    const size_t kvbase = (size_t)bh * NSEQ * PDIM;

    auto loadK = [&](int j0) {
#pragma unroll
        for (int u = 0; u < 8; u++) {
            int t = u >> 2;
            int idx = tid + (u & 3) * 256;
            int r  = (idx >> 3) & 127;
            int ch = idx & 7;
            uint32_t dst = sb + (t ? O_KLO : O_KHI) + r * 128 + ((ch ^ (r & 7)) << 4);
            cp16(dst, (t ? klo : khi) + kvbase + (size_t)(j0 + r) * PDIM + ch * 8);
        }
        cp_commit();
    };
    auto loadV = [&](int j0) {
#pragma unroll
        for (int u = 0; u < 8; u++) {
            int t = u >> 2;
            int idx = tid + (u & 3) * 256;
            int r  = (idx >> 3) & 127;
            int ch = idx & 7;
            uint32_t dst = sb + (t ? O_VLO : O_VHI) + r * 128 + ((ch ^ (r & 7)) << 4);
            cp16(dst, (t ? vlo : vhi) + kvbase + (size_t)(j0 + r) * PDIM + ch * 8);
        }
        cp_commit();
    };
    auto loadE = [&](int j0) {
        const int eb2 = i0 - j0 + 896;
#pragma unroll
        for (int u = 0; u < 16; u++) {
            int t = u >> 3;
            int idx = tid + (u & 7) * 256;
            int r  = (idx >> 3) & 255;
            int ch = idx & 7;
            uint32_t dst = sb + (t ? O_ELO : O_EHI) + r * 128 + ((ch ^ (r & 7)) << 4);
            cp16(dst, (t ? elo : ehi) + (size_t)(eb2 + r) * PDIM + ch * 8);
        }
        cp_commit();
    };

    // group G1 = Q + K(0)
#pragma unroll
    for (int u = 0; u < 8; u++) {
        int t  = u >> 2;
        int idx = tid + (u & 3) * 256;
        int r  = (idx >> 3) & 127;
        int ch = idx & 7;
        uint32_t dst = sb + (t ? O_QLO : O_QHI) + r * 128 + ((ch ^ (r & 7)) << 4);
        cp16(dst, (t ? qlo : qhi) + qoff + (size_t)r * PDIM + ch * 8);
    }
    loadK(0);      // commits G1
    loadE(0);      // commits G2

    float oacc[8][4];
#pragma unroll
    for (int nt = 0; nt < 8; nt++)
#pragma unroll
        for (int q = 0; q < 4; q++) oacc[nt][q] = 0.f;
    float m_run[2] = {-1e30f, -1e30f}, l_run[2] = {0.f, 0.f};

    uint32_t qh[4][4], ql[4][4];          // hoisted Q fragments (per kk)
    float* PSTf = (float*)(smc + O_PST);
    float* PW = PSTf + w * 1344;          // per-warp 16 x 84 fp32 stage

    for (int jt = 0; jt < 8; jt++) {
        const int j0 = jt * 128;
        __syncthreads();                   // prior PV / p reads complete
        loadV(j0);                         // group V_jt
        cp_wait2();                        // K(jt) (+Q at jt=0) complete
        __syncthreads();

        if (jt == 0) {
#pragma unroll
            for (int kk = 0; kk < 4; kk++) {
                uint32_t chsw = ((uint32_t)(2 * kk + lhalf) ^ (lrow & 7)) << 4;
                ldm_x4(qh[kk], sb + O_QHI + (w * 16 + lrow) * 128 + chsw);
                ldm_x4(ql[kk], sb + O_QLO + (w * 16 + lrow) * 128 + chsw);
            }
        }

        // ---- S = QK^T (3-term split) ----
        float s[16][4];
#pragma unroll
        for (int nt = 0; nt < 16; nt++)
#pragma unroll
            for (int q = 0; q < 4; q++) s[nt][q] = 0.f;

#pragma unroll
        for (int kk = 0; kk < 4; kk++) {
            const uint32_t chsw = ((uint32_t)(2 * kk + lhalf) ^ (lrow & 7)) << 4;
            uint32_t kb[8][4];
#pragma unroll
            for (int np = 0; np < 8; np++)
                ldm_x4(kb[np], sb + O_KHI + (np * 16 + lrow) * 128 + chsw);
#pragma unroll
            for (int nt = 0; nt < 16; nt++)
                mma_bf16(s[nt], qh[kk], kb[nt >> 1][nt & 1], kb[nt >> 1][2 + (nt & 1)]);
#pragma unroll
            for (int nt = 0; nt < 16; nt++)
                mma_bf16(s[nt], ql[kk], kb[nt >> 1][nt & 1], kb[nt >> 1][2 + (nt & 1)]);
#pragma unroll
            for (int np = 0; np < 8; np++)
                ldm_x4(kb[np], sb + O_KLO + (np * 16 + lrow) * 128 + chsw);
#pragma unroll
            for (int nt = 0; nt < 16; nt++)
                mma_bf16(s[nt], qh[kk], kb[nt >> 1][nt & 1], kb[nt >> 1][2 + (nt & 1)]);
        }

        __syncthreads();                   // K smem dead
        if (jt < 7) loadK(j0 + 128);       // prefetch next K
        if (jt < 7) cp_wait2(); else cp_wait1();   // E(jt) complete
        __syncthreads();

        // ---- bias: per-warp window E rows [w16, w16+143], 2 chunks ----
        const int wb = w * 16;
#pragma unroll
        for (int q = 0; q < 2; q++) {
            const int roff = q ? 80 : 0;
            const int NT = q ? 8 : 10;
            float p[10][4];
#pragma unroll
            for (int nt = 0; nt < 10; nt++)
#pragma unroll
                for (int e = 0; e < 4; e++) p[nt][e] = 0.f;

#pragma unroll
            for (int kk = 0; kk < 4; kk++) {
                const uint32_t chsw = ((uint32_t)(2 * kk + lhalf) ^ (lrow & 7)) << 4;
                uint32_t eb[5][4];
#pragma unroll
                for (int np = 0; np < (NT + 1) / 2; np++)
                    ldm_x4(eb[np], sb + O_EHI +
                           (wb + roff + np * 16 + lrow) * 128 + chsw);
#pragma unroll
                for (int nt = 0; nt < NT; nt++)
                    mma_bf16(p[nt], qh[kk], eb[nt >> 1][nt & 1], eb[nt >> 1][2 + (nt & 1)]);
#pragma unroll
                for (int nt = 0; nt < NT; nt++)
                    mma_bf16(p[nt], ql[kk], eb[nt >> 1][nt & 1], eb[nt >> 1][2 + (nt & 1)]);
#pragma unroll
                for (int np = 0; np < (NT + 1) / 2; np++)
                    ldm_x4(eb[np], sb + O_ELO +
                           (wb + roff + np * 16 + lrow) * 128 + chsw);
#pragma unroll
                for (int nt = 0; nt < NT; nt++)
                    mma_bf16(p[nt], qh[kk], eb[nt >> 1][nt & 1], eb[nt >> 1][2 + (nt & 1)]);
            }
            // stage into own-warp buffer
#pragma unroll
            for (int nt = 0; nt < NT; nt++) {
                int col = nt * 8 + 2 * lr4;
                *(float2*)&PW[lq * 84 + col] = make_float2(p[nt][0], p[nt][1]);
                *(float2*)&PW[(lq + 8) * 84 + col] = make_float2(p[nt][2], p[nt][3]);
            }
            __syncwarp();
            // diagonal gather: pwl = rl - c + 127 in [0,142]
#pragma unroll
            for (int nt = 0; nt < 16; nt++)
#pragma unroll
                for (int idx = 0; idx < 4; idx++) {
                    int rl = lq + (idx >> 1) * 8;
                    int c = nt * 8 + 2 * lr4 + (idx & 1);
                    int pwl = rl - c + 127;
                    bool sel = q ? (pwl >= 80) : (pwl < 80);
                    if (sel) s[nt][idx] += PW[rl * 84 + pwl - roff];
                }
            __syncwarp();
        }

        __syncthreads();                   // all gathers done (PST dead)
        if (jt < 7) loadE(j0 + 128);       // prefetch next E

        // ---- online softmax ----
#pragma unroll
        for (int h2 = 0; h2 < 2; h2++) {
            float mx = -1e30f;
#pragma unroll
            for (int nt = 0; nt < 16; nt++)
                mx = fmaxf(mx, fmaxf(s[nt][h2 * 2], s[nt][h2 * 2 + 1]));
            mx = fmaxf(mx, __shfl_xor_sync(0xffffffffu, mx, 1));
            mx = fmaxf(mx, __shfl_xor_sync(0xffffffffu, mx, 2));
            float m_new = fmaxf(m_run[h2], mx);
            float scl = __expf(m_run[h2] - m_new);
            m_run[h2] = m_new;
            float rs = 0.f;
#pragma unroll
            for (int nt = 0; nt < 16; nt++) {
                float e0 = __expf(s[nt][h2 * 2] - m_new);
                float e1 = __expf(s[nt][h2 * 2 + 1] - m_new);
                s[nt][h2 * 2] = e0;
                s[nt][h2 * 2 + 1] = e1;
                rs += e0 + e1;
            }
            rs += __shfl_xor_sync(0xffffffffu, rs, 1);
            rs += __shfl_xor_sync(0xffffffffu, rs, 2);
            l_run[h2] = l_run[h2] * scl + rs;
#pragma unroll
            for (int nt = 0; nt < 8; nt++) {
                oacc[nt][h2 * 2] *= scl;
                oacc[nt][h2 * 2 + 1] *= scl;
            }
        }

        // ---- write p hi/lo tiles ----
#pragma unroll
        for (int nt = 0; nt < 16; nt++)
#pragma unroll
            for (int h2 = 0; h2 < 2; h2++) {
                int row = w * 16 + lq + h2 * 8;
                int c = nt * 8 + 2 * lr4;
                float p0 = s[nt][h2 * 2], p1 = s[nt][h2 * 2 + 1];
                float h0 = __bfloat162float(__float2bfloat16(p0));
                float h1 = __bfloat162float(__float2bfloat16(p1));
                uint32_t off = row * 256 + (((c >> 3) ^ (row & 7)) << 4) + (c & 7) * 2;
                *(uint32_t*)(smc + O_PHI + off) = pack_bf16x2(p0, p1);
                *(uint32_t*)(smc + O_PLO + off) = pack_bf16x2(p0 - h0, p1 - h1);
            }

        if (jt < 7) cp_wait2(); else cp_wait0();   // V(jt) complete
        __syncthreads();                   // V + p visible to all

        // ---- PV (3-term split), V via ldmatrix.trans ----
#pragma unroll
        for (int kk = 0; kk < 8; kk++) {
            uint32_t ah[4], al[4], vb[4][4];
            {
                uint32_t chA = (uint32_t)(2 * kk + lhalf);
                uint32_t aoff = (w * 16 + lrow) * 256 + ((chA ^ (lrow & 7)) << 4);
                ldm_x4(ah, sb + O_PHI + aoff);
                ldm_x4(al, sb + O_PLO + aoff);
            }
            const uint32_t vrow = kk * 16 + lrow;
#pragma unroll
            for (int np = 0; np < 4; np++)
                ldm_x4t(vb[np], sb + O_VHI + vrow * 128 +
                        ((((uint32_t)(np * 2 + lhalf)) ^ (lrow & 7)) << 4));
#pragma unroll
            for (int nt = 0; nt < 8; nt++)
                mma_bf16(oacc[nt], ah, vb[nt >> 1][(nt & 1) * 2],
                         vb[nt >> 1][(nt & 1) * 2 + 1]);
#pragma unroll
            for (int nt = 0; nt < 8; nt++)
                mma_bf16(oacc[nt], al, vb[nt >> 1][(nt & 1) * 2],
                         vb[nt >> 1][(nt & 1) * 2 + 1]);
#pragma unroll
            for (int np = 0; np < 4; np++)
                ldm_x4t(vb[np], sb + O_VLO + vrow * 128 +
                        ((((uint32_t)(np * 2 + lhalf)) ^ (lrow & 7)) << 4));
#pragma unroll
            for (int nt = 0; nt < 8; nt++)
                mma_bf16(oacc[nt], ah, vb[nt >> 1][(nt & 1) * 2],
                         vb[nt >> 1][(nt & 1) * 2 + 1]);
        }
    }

    // ---- final normalize + write ----
#pragma unroll
    for (int h2 = 0; h2 < 2; h2++) {
        float inv = 1.f / l_run[h2];
        int r_glob = i0 + w * 16 + lq + h2 * 8;
#pragma unroll
        for (int nt = 0; nt < 8; nt++) {
            int d = nt * 8 + 2 * lr4;
            *(float2*)(out + ((size_t)bb * NSEQ + r_glob) * DDIM + h * PDIM + d) =
                make_float2(oacc[nt][h2 * 2] * inv, oacc[nt][h2 * 2 + 1] * inv);
        }
    }
}

// ---------------------------------------------------------------------------
extern "C" void kernel_launch(void* const* d_in, const int* in_sizes, int n_in,
                              void* d_out, int out_size)
{
    const float* x  = (const float*)d_in[0];
    const float* wq = (const float*)d_in[1];
    const float* bq = (const float*)d_in[2];
    const float* wk = (const float*)d_in[3];
    const float* bk = (const float*)d_in[4];
    const float* wv = (const float*)d_in[5];
    const float* bv = (const float*)d_in[6];
    const float* de = (const float*)d_in[7];
    float* out = (float*)d_out;

    int B = in_sizes[0] / (NSEQ * DDIM);   // 8

    __nv_bfloat16 *xcat, *wcat, *qhi, *qlo, *khi, *klo, *vhi, *vlo, *ehi, *elo;
    cudaGetSymbolAddress((void**)&xcat, g_xcat);
    cudaGetSymbolAddress((void**)&wcat, g_wcat);
    cudaGetSymbolAddress((void**)&qhi, g_qhi);
    cudaGetSymbolAddress((void**)&qlo, g_qlo);
    cudaGetSymbolAddress((void**)&khi, g_khi);
    cudaGetSymbolAddress((void**)&klo, g_klo);
    cudaGetSymbolAddress((void**)&vhi, g_vhi);
    cudaGetSymbolAddress((void**)&vlo, g_vlo);
    cudaGetSymbolAddress((void**)&ehi, g_ehi);
    cudaGetSymbolAddress((void**)&elo, g_elo);

    cudaFuncSetAttribute(gemm_kernel,
                         cudaFuncAttributeMaxDynamicSharedMemorySize, GEMM_SMEM);
    cudaFuncSetAttribute(attn_kernel,
                         cudaFuncAttributeMaxDynamicSharedMemorySize, ATTN_SMEM);

    int nx4 = B * NSEQ * (DDIM / 4);
    int nw4 = DDIM * (DDIM / 4);
    split_kernel<<<(nx4 + 255) / 256, 256>>>(x, xcat, nx4, 2 * DDIM, DDIM);
    split_kernel<<<(nw4 + 255) / 256, 256>>>(wq, wcat + 0 * (size_t)DDIM * KCAT,
                                             nw4, DDIM, 2 * DDIM);
    split_kernel<<<(nw4 + 255) / 256, 256>>>(wk, wcat + 1 * (size_t)DDIM * KCAT,
                                             nw4, DDIM, 2 * DDIM);
    split_kernel<<<(nw4 + 255) / 256, 256>>>(wv, wcat + 2 * (size_t)DDIM * KCAT,
                                             nw4, DDIM, 2 * DDIM);
    esplit_kernel<<<128, 256>>>(de, ehi, elo);

    dim3 g1(B * NSEQ / 128, DDIM / 128, 3);
    gemm_kernel<<<g1, 256, GEMM_SMEM>>>(xcat, wcat, bq, bk, bv,
                                        qhi, qlo, khi, klo, vhi, vlo);

    dim3 g2(NSEQ / 128, HNUM, B);
    attn_kernel<<<g2, 256, ATTN_SMEM>>>(qhi, qlo, khi, klo, vhi, vlo,
                                        ehi, elo, out);
}